// round 1
// baseline (speedup 1.0000x reference)
#include <cuda_runtime.h>
#include <math.h>

#define T_TOK 4096
#define DIM   2048
#define H     128

// Scratch for projected Q, K, V (device globals: no allocation allowed)
__device__ float g_Q[T_TOK * H];
__device__ float g_K[T_TOK * H];
__device__ float g_V[T_TOK * H];

// ---------------------------------------------------------------------------
// QKV projection: C[T,H] = X[T,DIM] @ W[H,DIM]^T
// BM=64, BN=128(=H), BK=16, 256 threads, 4x8 per-thread tile.
// grid = (T/64, 3): blockIdx.y selects Q/K/V.
// ---------------------------------------------------------------------------
__global__ __launch_bounds__(256) void qkv_kernel(
    const float* __restrict__ X,
    const float* __restrict__ Wq,
    const float* __restrict__ Wk,
    const float* __restrict__ Wv)
{
    __shared__ float As[16][64];    // As[k][m]
    __shared__ float Bs[16][128];   // Bs[k][n]

    const float* W;
    float* C;
    if (blockIdx.y == 0)      { W = Wq; C = g_Q; }
    else if (blockIdx.y == 1) { W = Wk; C = g_K; }
    else                      { W = Wv; C = g_V; }

    const int tid = threadIdx.x;
    const int ty  = tid >> 4;         // 0..15 -> rows ty*4
    const int tx  = tid & 15;         // 0..15 -> cols tx*8
    const int m0  = blockIdx.x * 64;

    // A tile load mapping (1 float4/thread): lanes vary over row -> conflict-free STS
    const int ar   = tid & 63;
    const int ac4  = (tid >> 6) << 2;         // 0,4,8,12
    // B tile load mapping (2 float4/thread)
    const int br   = tid & 127;
    const int bc4  = (tid >> 7) << 2;         // 0 or 4 (second load adds +8)

    float acc[4][8];
    #pragma unroll
    for (int r = 0; r < 4; r++)
        #pragma unroll
        for (int c = 0; c < 8; c++) acc[r][c] = 0.f;

    for (int kk = 0; kk < DIM; kk += 16) {
        __syncthreads();
        {
            float4 av = *(const float4*)&X[(size_t)(m0 + ar) * DIM + kk + ac4];
            As[ac4 + 0][ar] = av.x;
            As[ac4 + 1][ar] = av.y;
            As[ac4 + 2][ar] = av.z;
            As[ac4 + 3][ar] = av.w;

            float4 b0 = *(const float4*)&W[(size_t)br * DIM + kk + bc4];
            float4 b1 = *(const float4*)&W[(size_t)br * DIM + kk + bc4 + 8];
            Bs[bc4 + 0][br] = b0.x;
            Bs[bc4 + 1][br] = b0.y;
            Bs[bc4 + 2][br] = b0.z;
            Bs[bc4 + 3][br] = b0.w;
            Bs[bc4 + 8][br] = b1.x;
            Bs[bc4 + 9][br] = b1.y;
            Bs[bc4 + 10][br] = b1.z;
            Bs[bc4 + 11][br] = b1.w;
        }
        __syncthreads();

        #pragma unroll
        for (int k = 0; k < 16; k++) {
            float4 t  = *(const float4*)&As[k][ty * 4];
            float4 u0 = *(const float4*)&Bs[k][tx * 8];
            float4 u1 = *(const float4*)&Bs[k][tx * 8 + 4];
            float a[4] = {t.x, t.y, t.z, t.w};
            float b[8] = {u0.x, u0.y, u0.z, u0.w, u1.x, u1.y, u1.z, u1.w};
            #pragma unroll
            for (int r = 0; r < 4; r++)
                #pragma unroll
                for (int c = 0; c < 8; c++)
                    acc[r][c] = fmaf(a[r], b[c], acc[r][c]);
        }
    }

    #pragma unroll
    for (int r = 0; r < 4; r++) {
        float* crow = &C[(size_t)(m0 + ty * 4 + r) * H + tx * 8];
        *(float4*)&crow[0] = make_float4(acc[r][0], acc[r][1], acc[r][2], acc[r][3]);
        *(float4*)&crow[4] = make_float4(acc[r][4], acc[r][5], acc[r][6], acc[r][7]);
    }
}

// ---------------------------------------------------------------------------
// Causal flash attention: BM=32 query rows per block, BN=128 keys per tile.
// 256 threads; thread (ty=tid/32, tx=tid%32) owns a 4x4 tile:
//   rows ty*4..+3, cols tx*4..+3. One warp == one ty -> full rows live in one
//   warp, so row reductions are pure 32-lane shuffles.
// SMEM layouts (all chosen for broadcast / conflict-free LDS.128):
//   Qs[k][m]  (128 x 32)  k-major (transposed)
//   Ks[k][n]  (128 x 128) k-major (transposed)
//   Vs[j][n]  (128 x 128) natural
//   Ps[j][m]  (128 x 36)  transposed, stride 36 for 16B-aligned rows
// ---------------------------------------------------------------------------
__global__ __launch_bounds__(256) void attn_kernel(float* __restrict__ out)
{
    extern __shared__ float sm[];
    float* Qs = sm;                    // 128*32   = 4096
    float* Ks = Qs + 128 * 32;         // 128*128  = 16384
    float* Vs = Ks + 128 * 128;        // 128*128  = 16384
    float* Ps = Vs + 128 * 128;        // 128*36   = 4608

    const int qt  = blockIdx.x;
    const int tid = threadIdx.x;
    const int ty  = tid >> 5;          // 0..7
    const int tx  = tid & 31;          // 0..31
    const float SCALE = 0.08838834764831843f;  // 1/sqrt(128)

    // Load Q tile transposed: Qs[k][m] = Q[qt*32+m][k]
    const float* Qg = g_Q + (size_t)qt * 32 * H;
    for (int i = tid; i < 32 * 32; i += 256) {
        int m = i & 31, kc = i >> 5;
        float4 v = *(const float4*)&Qg[m * H + kc * 4];
        Qs[(kc * 4 + 0) * 32 + m] = v.x;
        Qs[(kc * 4 + 1) * 32 + m] = v.y;
        Qs[(kc * 4 + 2) * 32 + m] = v.z;
        Qs[(kc * 4 + 3) * 32 + m] = v.w;
    }

    float mi[4], li[4], o[4][4];
    #pragma unroll
    for (int r = 0; r < 4; r++) {
        mi[r] = -INFINITY;
        li[r] = 0.f;
        #pragma unroll
        for (int c = 0; c < 4; c++) o[r][c] = 0.f;
    }

    const int n_kt = (qt * 32 + 31) / 128 + 1;
    for (int kt = 0; kt < n_kt; kt++) {
        __syncthreads();  // protect SMEM reuse from previous iteration
        const float* Kg = g_K + (size_t)kt * 128 * H;
        const float* Vg = g_V + (size_t)kt * 128 * H;
        // K transposed load: lanes vary over token n -> conflict-free STS
        for (int i = tid; i < 128 * 32; i += 256) {
            int n = i & 127, kc = i >> 7;
            float4 v = *(const float4*)&Kg[n * H + kc * 4];
            Ks[(kc * 4 + 0) * 128 + n] = v.x;
            Ks[(kc * 4 + 1) * 128 + n] = v.y;
            Ks[(kc * 4 + 2) * 128 + n] = v.z;
            Ks[(kc * 4 + 3) * 128 + n] = v.w;
        }
        // V natural copy, fully coalesced
        for (int i = tid; i < 128 * 32; i += 256)
            ((float4*)Vs)[i] = ((const float4*)Vg)[i];
        __syncthreads();

        // S = Q @ K^T  (thread 4x4 tile)
        float s[4][4];
        #pragma unroll
        for (int r = 0; r < 4; r++)
            #pragma unroll
            for (int c = 0; c < 4; c++) s[r][c] = 0.f;

        #pragma unroll 8
        for (int k = 0; k < 128; k++) {
            float4 a = *(const float4*)&Qs[k * 32 + ty * 4];   // warp broadcast
            float4 b = *(const float4*)&Ks[k * 128 + tx * 4];  // conflict-free
            float ar_[4] = {a.x, a.y, a.z, a.w};
            float bc_[4] = {b.x, b.y, b.z, b.w};
            #pragma unroll
            for (int r = 0; r < 4; r++)
                #pragma unroll
                for (int c = 0; c < 4; c++)
                    s[r][c] = fmaf(ar_[r], bc_[c], s[r][c]);
        }

        // scale + causal mask + online softmax (row = warp)
        const int rowg = qt * 32 + ty * 4;
        const int colg = kt * 128 + tx * 4;
        #pragma unroll
        for (int r = 0; r < 4; r++) {
            #pragma unroll
            for (int c = 0; c < 4; c++) {
                float v = s[r][c] * SCALE;
                s[r][c] = (colg + c > rowg + r) ? -INFINITY : v;
            }
            float mx = fmaxf(fmaxf(s[r][0], s[r][1]), fmaxf(s[r][2], s[r][3]));
            #pragma unroll
            for (int off = 16; off > 0; off >>= 1)
                mx = fmaxf(mx, __shfl_xor_sync(0xffffffffu, mx, off));
            float mnew = fmaxf(mi[r], mx);
            float corr = __expf(mi[r] - mnew);
            float rs = 0.f;
            #pragma unroll
            for (int c = 0; c < 4; c++) {
                float p = __expf(s[r][c] - mnew);
                s[r][c] = p;
                rs += p;
            }
            #pragma unroll
            for (int off = 16; off > 0; off >>= 1)
                rs += __shfl_xor_sync(0xffffffffu, rs, off);
            li[r] = li[r] * corr + rs;
            mi[r] = mnew;
            #pragma unroll
            for (int c = 0; c < 4; c++) o[r][c] *= corr;
        }

        // store P transposed: Ps[j][m], pack 4 rows per STS.128
        #pragma unroll
        for (int c = 0; c < 4; c++) {
            *(float4*)&Ps[(tx * 4 + c) * 36 + ty * 4] =
                make_float4(s[0][c], s[1][c], s[2][c], s[3][c]);
        }
        __syncthreads();

        // O += P @ V
        #pragma unroll 8
        for (int j = 0; j < 128; j++) {
            float4 p = *(const float4*)&Ps[j * 36 + ty * 4];   // warp broadcast
            float4 v = *(const float4*)&Vs[j * 128 + tx * 4];  // conflict-free
            float pr[4] = {p.x, p.y, p.z, p.w};
            float vc[4] = {v.x, v.y, v.z, v.w};
            #pragma unroll
            for (int r = 0; r < 4; r++)
                #pragma unroll
                for (int c = 0; c < 4; c++)
                    o[r][c] = fmaf(pr[r], vc[c], o[r][c]);
        }
    }

    // normalize + write
    #pragma unroll
    for (int r = 0; r < 4; r++) {
        float inv = 1.f / li[r];
        *(float4*)&out[(size_t)(qt * 32 + ty * 4 + r) * H + tx * 4] =
            make_float4(o[r][0] * inv, o[r][1] * inv, o[r][2] * inv, o[r][3] * inv);
    }
}

// ---------------------------------------------------------------------------
extern "C" void kernel_launch(void* const* d_in, const int* in_sizes, int n_in,
                              void* d_out, int out_size)
{
    const float* x  = (const float*)d_in[0];
    const float* Wq = (const float*)d_in[1];
    const float* Wk = (const float*)d_in[2];
    const float* Wv = (const float*)d_in[3];
    float* out = (float*)d_out;

    dim3 grid_qkv(T_TOK / 64, 3);
    qkv_kernel<<<grid_qkv, 256>>>(x, Wq, Wk, Wv);

    const int smem_bytes = (128 * 32 + 2 * 128 * 128 + 128 * 36) * (int)sizeof(float);
    cudaFuncSetAttribute(attn_kernel,
                         cudaFuncAttributeMaxDynamicSharedMemorySize, smem_bytes);
    attn_kernel<<<T_TOK / 32, 256, smem_bytes>>>(out);
}

// round 3
// speedup vs baseline: 2.3945x; 2.3945x over previous
#include <cuda_runtime.h>
#include <cuda_bf16.h>
#include <math.h>
#include <stdint.h>

#define T_TOK 4096
#define DIM   2048
#define H     128
#define NCH   8        // max KV chunks per query tile (32 key tiles / 4)

// ---------------- device scratch (no allocation allowed) --------------------
__device__ float g_Q[T_TOK * H];
__device__ float g_K[T_TOK * H];
__device__ float g_V[T_TOK * H];
__device__ __nv_bfloat16 g_Xhi[T_TOK * DIM];
__device__ __nv_bfloat16 g_Xlo[T_TOK * DIM];
__device__ __nv_bfloat16 g_Whi[3 * H * DIM];
__device__ __nv_bfloat16 g_Wlo[3 * H * DIM];
__device__ float g_pO[128 * NCH * 32 * H];   // unnormalized partial outputs
__device__ float g_pm[128 * NCH * 32];       // partial row max
__device__ float g_pl[128 * NCH * 32];       // partial row sum

// ---------------------------------------------------------------------------
// warp-level bf16 MMA (sm_80+ baseline; legal on plain compute_103)
// D(16x8,f32) += A(16x16,bf16,row) * B(16x8,bf16,col)
// ---------------------------------------------------------------------------
__device__ __forceinline__ void mma16816(float* c, const uint32_t* a, const uint32_t* b)
{
    asm volatile(
        "mma.sync.aligned.m16n8k16.row.col.f32.bf16.bf16.f32 "
        "{%0,%1,%2,%3}, {%4,%5,%6,%7}, {%8,%9}, {%0,%1,%2,%3};"
        : "+f"(c[0]), "+f"(c[1]), "+f"(c[2]), "+f"(c[3])
        : "r"(a[0]), "r"(a[1]), "r"(a[2]), "r"(a[3]), "r"(b[0]), "r"(b[1]));
}

// ---------------------------------------------------------------------------
// fp32 -> (bf16 hi, bf16 lo) split. dest: 0=X, 1..3=Wq/Wk/Wv
// ---------------------------------------------------------------------------
__global__ __launch_bounds__(256) void cvt_kernel(const float* __restrict__ in,
                                                  int dest, int n)
{
    __nv_bfloat16 *hi, *lo;
    if (dest == 0) { hi = g_Xhi; lo = g_Xlo; }
    else           { hi = g_Whi + (size_t)(dest - 1) * H * DIM;
                     lo = g_Wlo + (size_t)(dest - 1) * H * DIM; }
    int i = (blockIdx.x * 256 + threadIdx.x) * 8;
    if (i >= n) return;
    float4 a = *(const float4*)(in + i);
    float4 b = *(const float4*)(in + i + 4);
    float xs[8] = {a.x, a.y, a.z, a.w, b.x, b.y, b.z, b.w};
    __nv_bfloat16 hs[8], ls[8];
    #pragma unroll
    for (int j = 0; j < 8; j++) {
        __nv_bfloat16 h = __float2bfloat16(xs[j]);
        hs[j] = h;
        ls[j] = __float2bfloat16(xs[j] - __bfloat162float(h));
    }
    uint4 hv, lv;
    {
        __nv_bfloat162 t;
        t = __halves2bfloat162(hs[0], hs[1]); hv.x = *(uint32_t*)&t;
        t = __halves2bfloat162(hs[2], hs[3]); hv.y = *(uint32_t*)&t;
        t = __halves2bfloat162(hs[4], hs[5]); hv.z = *(uint32_t*)&t;
        t = __halves2bfloat162(hs[6], hs[7]); hv.w = *(uint32_t*)&t;
        t = __halves2bfloat162(ls[0], ls[1]); lv.x = *(uint32_t*)&t;
        t = __halves2bfloat162(ls[2], ls[3]); lv.y = *(uint32_t*)&t;
        t = __halves2bfloat162(ls[4], ls[5]); lv.z = *(uint32_t*)&t;
        t = __halves2bfloat162(ls[6], ls[7]); lv.w = *(uint32_t*)&t;
    }
    *(uint4*)(hi + i) = hv;
    *(uint4*)(lo + i) = lv;
}

// ---------------------------------------------------------------------------
// QKV GEMM via mma.sync bf16x3: C[m,n] = sum_k X[m,k] * W[n,k]
//   X ~ Xhi + Xlo, W ~ Whi + Wlo; C = Ahi*Bhi + Ahi*Blo + Alo*Bhi
// BM=128, BN=128(=H), BK=32. 256 threads = 8 warps, warp tile 32m x 64n
// (warp grid 4m x 2n). smem padded to stride 40 bf16 (conflict-free frags).
// grid = (32, 3).
// ---------------------------------------------------------------------------
#define SKS 40                 // smem k-stride in bf16
#define QKV_ITERS (DIM / 32)   // 64

__global__ __launch_bounds__(256) void qkv_mma_kernel()
{
    __shared__ __nv_bfloat16 sA[2][128 * SKS];   // [hi/lo][row][k]
    __shared__ __nv_bfloat16 sB[2][128 * SKS];

    const int tid = threadIdx.x;
    const int wid = tid >> 5;
    const int lid = tid & 31;
    const int wm  = wid & 3;          // 0..3 -> m offset wm*32
    const int wn  = wid >> 2;         // 0..1 -> n offset wn*64
    const int m0  = blockIdx.x * 128;
    const int widx = blockIdx.y;

    const __nv_bfloat16* Ahi = g_Xhi + (size_t)m0 * DIM;
    const __nv_bfloat16* Alo = g_Xlo + (size_t)m0 * DIM;
    const __nv_bfloat16* Bhi = g_Whi + (size_t)widx * H * DIM;
    const __nv_bfloat16* Blo = g_Wlo + (size_t)widx * H * DIM;

    // loader mapping: rows tid/4 and tid/4+64, col chunk q = tid%4 (8 bf16)
    const int lr = tid >> 2;
    const int lq = tid & 3;

    float acc[2][8][4];
    #pragma unroll
    for (int im = 0; im < 2; im++)
        #pragma unroll
        for (int in = 0; in < 8; in++)
            #pragma unroll
            for (int q = 0; q < 4; q++) acc[im][in][q] = 0.f;

    // prefetch slab 0
    uint4 rah[2], ral[2], rbh[2], rbl[2];
    #pragma unroll
    for (int g = 0; g < 2; g++) {
        size_t goA = (size_t)(lr + g * 64) * DIM + lq * 8;
        rah[g] = *(const uint4*)(Ahi + goA);
        ral[g] = *(const uint4*)(Alo + goA);
        rbh[g] = *(const uint4*)(Bhi + goA);
        rbl[g] = *(const uint4*)(Blo + goA);
    }

    for (int kc = 0; kc < QKV_ITERS; kc++) {
        __syncthreads();   // previous compute done with smem
        #pragma unroll
        for (int g = 0; g < 2; g++) {
            int so = (lr + g * 64) * SKS + lq * 8;
            *(uint4*)&sA[0][so] = rah[g];
            *(uint4*)&sA[1][so] = ral[g];
            *(uint4*)&sB[0][so] = rbh[g];
            *(uint4*)&sB[1][so] = rbl[g];
        }
        __syncthreads();

        // prefetch next slab (overlaps with compute below)
        if (kc + 1 < QKV_ITERS) {
            #pragma unroll
            for (int g = 0; g < 2; g++) {
                size_t goA = (size_t)(lr + g * 64) * DIM + (kc + 1) * 32 + lq * 8;
                rah[g] = *(const uint4*)(Ahi + goA);
                ral[g] = *(const uint4*)(Alo + goA);
                rbh[g] = *(const uint4*)(Bhi + goA);
                rbl[g] = *(const uint4*)(Blo + goA);
            }
        }

        // compute on current slab: 2 k16 substeps
        #pragma unroll
        for (int ks = 0; ks < 2; ks++) {
            const int k0 = ks * 16 + (lid & 3) * 2;
            uint32_t ah[2][4], al[2][4];
            #pragma unroll
            for (int im = 0; im < 2; im++) {
                int r0 = wm * 32 + im * 16 + (lid >> 2);
                ah[im][0] = *(const uint32_t*)&sA[0][r0 * SKS + k0];
                ah[im][1] = *(const uint32_t*)&sA[0][(r0 + 8) * SKS + k0];
                ah[im][2] = *(const uint32_t*)&sA[0][r0 * SKS + k0 + 8];
                ah[im][3] = *(const uint32_t*)&sA[0][(r0 + 8) * SKS + k0 + 8];
                al[im][0] = *(const uint32_t*)&sA[1][r0 * SKS + k0];
                al[im][1] = *(const uint32_t*)&sA[1][(r0 + 8) * SKS + k0];
                al[im][2] = *(const uint32_t*)&sA[1][r0 * SKS + k0 + 8];
                al[im][3] = *(const uint32_t*)&sA[1][(r0 + 8) * SKS + k0 + 8];
            }
            #pragma unroll
            for (int in = 0; in < 8; in++) {
                int n = wn * 64 + in * 8 + (lid >> 2);
                uint32_t bh[2], bl[2];
                bh[0] = *(const uint32_t*)&sB[0][n * SKS + k0];
                bh[1] = *(const uint32_t*)&sB[0][n * SKS + k0 + 8];
                bl[0] = *(const uint32_t*)&sB[1][n * SKS + k0];
                bl[1] = *(const uint32_t*)&sB[1][n * SKS + k0 + 8];
                #pragma unroll
                for (int im = 0; im < 2; im++) {
                    mma16816(acc[im][in], ah[im], bh);
                    mma16816(acc[im][in], ah[im], bl);
                    mma16816(acc[im][in], al[im], bh);
                }
            }
        }
    }

    // write C
    float* Cout = (widx == 0) ? g_Q : (widx == 1) ? g_K : g_V;
    #pragma unroll
    for (int im = 0; im < 2; im++) {
        int r0 = m0 + wm * 32 + im * 16 + (lid >> 2);
        #pragma unroll
        for (int in = 0; in < 8; in++) {
            int c0 = wn * 64 + in * 8 + (lid & 3) * 2;
            *(float2*)&Cout[(size_t)r0 * H + c0] =
                make_float2(acc[im][in][0], acc[im][in][1]);
            *(float2*)&Cout[(size_t)(r0 + 8) * H + c0] =
                make_float2(acc[im][in][2], acc[im][in][3]);
        }
    }
}

// ---------------------------------------------------------------------------
// Split-KV causal flash attention partial pass.
// grid = (128 query tiles of BM=32, NCH chunk slots). Chunk = 4 key tiles
// of BN=128 (512 keys). Writes unnormalized O + (m, l) per row.
// ---------------------------------------------------------------------------
__global__ __launch_bounds__(256) void attn_partial_kernel()
{
    const int qt = blockIdx.x;
    const int ci = blockIdx.y;
    const int n_kt = (qt >> 2) + 1;
    const int kt0 = ci * 4;
    if (kt0 >= n_kt) return;
    const int kt1 = (kt0 + 4 < n_kt) ? kt0 + 4 : n_kt;

    extern __shared__ float sm[];
    float* Qs = sm;                    // 128 x 32  (k-major)
    float* Ks = Qs + 128 * 32;         // 128 x 128 (k-major)
    float* Vs = Ks + 128 * 128;        // 128 x 128 (natural)
    float* Ps = Vs + 128 * 128;        // 128 x 36  (transposed, padded)

    const int tid = threadIdx.x;
    const int ty  = tid >> 5;
    const int tx  = tid & 31;
    const float SCALE = 0.08838834764831843f;

    const float* Qg = g_Q + (size_t)qt * 32 * H;
    for (int i = tid; i < 32 * 32; i += 256) {
        int m = i & 31, kcc = i >> 5;
        float4 v = *(const float4*)&Qg[m * H + kcc * 4];
        Qs[(kcc * 4 + 0) * 32 + m] = v.x;
        Qs[(kcc * 4 + 1) * 32 + m] = v.y;
        Qs[(kcc * 4 + 2) * 32 + m] = v.z;
        Qs[(kcc * 4 + 3) * 32 + m] = v.w;
    }

    float mi[4], li[4], o[4][4];
    #pragma unroll
    for (int r = 0; r < 4; r++) {
        mi[r] = -INFINITY; li[r] = 0.f;
        #pragma unroll
        for (int c = 0; c < 4; c++) o[r][c] = 0.f;
    }

    for (int kt = kt0; kt < kt1; kt++) {
        __syncthreads();
        const float* Kg = g_K + (size_t)kt * 128 * H;
        const float* Vg = g_V + (size_t)kt * 128 * H;
        for (int i = tid; i < 128 * 32; i += 256) {
            int n = i & 127, kcc = i >> 7;
            float4 v = *(const float4*)&Kg[n * H + kcc * 4];
            Ks[(kcc * 4 + 0) * 128 + n] = v.x;
            Ks[(kcc * 4 + 1) * 128 + n] = v.y;
            Ks[(kcc * 4 + 2) * 128 + n] = v.z;
            Ks[(kcc * 4 + 3) * 128 + n] = v.w;
        }
        for (int i = tid; i < 128 * 32; i += 256)
            ((float4*)Vs)[i] = ((const float4*)Vg)[i];
        __syncthreads();

        float s[4][4];
        #pragma unroll
        for (int r = 0; r < 4; r++)
            #pragma unroll
            for (int c = 0; c < 4; c++) s[r][c] = 0.f;

        #pragma unroll 8
        for (int k = 0; k < 128; k++) {
            float4 a = *(const float4*)&Qs[k * 32 + ty * 4];
            float4 b = *(const float4*)&Ks[k * 128 + tx * 4];
            float ar_[4] = {a.x, a.y, a.z, a.w};
            float bc_[4] = {b.x, b.y, b.z, b.w};
            #pragma unroll
            for (int r = 0; r < 4; r++)
                #pragma unroll
                for (int c = 0; c < 4; c++)
                    s[r][c] = fmaf(ar_[r], bc_[c], s[r][c]);
        }

        const int rowg = qt * 32 + ty * 4;
        const int colg = kt * 128 + tx * 4;
        #pragma unroll
        for (int r = 0; r < 4; r++) {
            #pragma unroll
            for (int c = 0; c < 4; c++) {
                float v = s[r][c] * SCALE;
                s[r][c] = (colg + c > rowg + r) ? -INFINITY : v;
            }
            float mx = fmaxf(fmaxf(s[r][0], s[r][1]), fmaxf(s[r][2], s[r][3]));
            #pragma unroll
            for (int off = 16; off > 0; off >>= 1)
                mx = fmaxf(mx, __shfl_xor_sync(0xffffffffu, mx, off));
            float mnew = fmaxf(mi[r], mx);
            float corr = __expf(mi[r] - mnew);
            float rs = 0.f;
            #pragma unroll
            for (int c = 0; c < 4; c++) {
                float p = __expf(s[r][c] - mnew);
                s[r][c] = p;
                rs += p;
            }
            #pragma unroll
            for (int off = 16; off > 0; off >>= 1)
                rs += __shfl_xor_sync(0xffffffffu, rs, off);
            li[r] = li[r] * corr + rs;
            mi[r] = mnew;
            #pragma unroll
            for (int c = 0; c < 4; c++) o[r][c] *= corr;
        }

        #pragma unroll
        for (int c = 0; c < 4; c++) {
            *(float4*)&Ps[(tx * 4 + c) * 36 + ty * 4] =
                make_float4(s[0][c], s[1][c], s[2][c], s[3][c]);
        }
        __syncthreads();

        #pragma unroll 8
        for (int j = 0; j < 128; j++) {
            float4 p = *(const float4*)&Ps[j * 36 + ty * 4];
            float4 v = *(const float4*)&Vs[j * 128 + tx * 4];
            float pr[4] = {p.x, p.y, p.z, p.w};
            float vc[4] = {v.x, v.y, v.z, v.w};
            #pragma unroll
            for (int r = 0; r < 4; r++)
                #pragma unroll
                for (int c = 0; c < 4; c++)
                    o[r][c] = fmaf(pr[r], vc[c], o[r][c]);
        }
    }

    // write unnormalized partials
    const int slot = qt * NCH + ci;
    #pragma unroll
    for (int r = 0; r < 4; r++) {
        *(float4*)&g_pO[(size_t)slot * 32 * H + (ty * 4 + r) * H + tx * 4] =
            make_float4(o[r][0], o[r][1], o[r][2], o[r][3]);
        if (tx == 0) {
            g_pm[slot * 32 + ty * 4 + r] = mi[r];
            g_pl[slot * 32 + ty * 4 + r] = li[r];
        }
    }
}

// ---------------------------------------------------------------------------
// Combine partials: out = (sum_i O_i * e^{m_i - M}) / (sum_i l_i * e^{m_i - M})
// grid = 128 (query tiles), 256 threads.
// ---------------------------------------------------------------------------
__global__ __launch_bounds__(256) void combine_kernel(float* __restrict__ out)
{
    const int qt = blockIdx.x;
    const int n_kt = (qt >> 2) + 1;
    const int n_ch = (n_kt + 3) >> 2;

    __shared__ float sm_m[NCH][32], sm_l[NCH][32];
    const int tid = threadIdx.x;
    {
        int i = tid >> 5, row = tid & 31;
        float m = -INFINITY, l = 0.f;
        if (i < n_ch) {
            m = g_pm[(qt * NCH + i) * 32 + row];
            l = g_pl[(qt * NCH + i) * 32 + row];
        }
        sm_m[i][row] = m;
        sm_l[i][row] = l;
    }
    __syncthreads();

    const int row = tid >> 3, j = tid & 7, col0 = j * 16;
    float M = -INFINITY;
    for (int i = 0; i < n_ch; i++) M = fmaxf(M, sm_m[i][row]);
    float L = 0.f;
    float w[NCH];
    for (int i = 0; i < n_ch; i++) {
        w[i] = __expf(sm_m[i][row] - M);
        L += w[i] * sm_l[i][row];
    }
    const float invL = 1.f / L;

    #pragma unroll
    for (int c4 = 0; c4 < 4; c4++) {
        float4 acc = make_float4(0.f, 0.f, 0.f, 0.f);
        for (int i = 0; i < n_ch; i++) {
            float4 v = *(const float4*)&g_pO[(size_t)(qt * NCH + i) * 32 * H +
                                             row * H + col0 + c4 * 4];
            acc.x += w[i] * v.x; acc.y += w[i] * v.y;
            acc.z += w[i] * v.z; acc.w += w[i] * v.w;
        }
        *(float4*)&out[((size_t)qt * 32 + row) * H + col0 + c4 * 4] =
            make_float4(acc.x * invL, acc.y * invL, acc.z * invL, acc.w * invL);
    }
}

// ---------------------------------------------------------------------------
extern "C" void kernel_launch(void* const* d_in, const int* in_sizes, int n_in,
                              void* d_out, int out_size)
{
    const float* x  = (const float*)d_in[0];
    const float* Wq = (const float*)d_in[1];
    const float* Wk = (const float*)d_in[2];
    const float* Wv = (const float*)d_in[3];
    float* out = (float*)d_out;

    cvt_kernel<<<T_TOK * DIM / 2048, 256>>>(x, 0, T_TOK * DIM);
    cvt_kernel<<<H * DIM / 2048, 256>>>(Wq, 1, H * DIM);
    cvt_kernel<<<H * DIM / 2048, 256>>>(Wk, 2, H * DIM);
    cvt_kernel<<<H * DIM / 2048, 256>>>(Wv, 3, H * DIM);

    qkv_mma_kernel<<<dim3(32, 3), 256>>>();

    const int attn_smem = (128 * 32 + 2 * 128 * 128 + 128 * 36) * (int)sizeof(float);
    cudaFuncSetAttribute(attn_partial_kernel,
                         cudaFuncAttributeMaxDynamicSharedMemorySize, attn_smem);
    attn_partial_kernel<<<dim3(128, NCH), 256, attn_smem>>>();

    combine_kernel<<<128, 256>>>(out);
}

// round 4
// speedup vs baseline: 3.9397x; 1.6453x over previous
#include <cuda_runtime.h>
#include <cuda_bf16.h>
#include <math.h>
#include <stdint.h>

#define T_TOK 4096
#define DIM   2048
#define H     128
#define NCH   8        // max KV chunks per query tile (32 key tiles / 4)
#define NQT   32       // query tiles of 128 rows
#define SKS2  136      // attn smem stride (bf16)

// ---------------- device scratch (no allocation allowed) --------------------
__device__ __nv_bfloat16 g_Xhi[T_TOK * DIM];
__device__ __nv_bfloat16 g_Xlo[T_TOK * DIM];
__device__ __nv_bfloat16 g_Whi[3 * H * DIM];
__device__ __nv_bfloat16 g_Wlo[3 * H * DIM];
__device__ __nv_bfloat16 g_Qhi[T_TOK * H], g_Qlo[T_TOK * H];
__device__ __nv_bfloat16 g_Khi[T_TOK * H], g_Klo[T_TOK * H];
__device__ __nv_bfloat16 g_Vhi[T_TOK * H], g_Vlo[T_TOK * H];
__device__ float g_pO[NQT * NCH * 128 * H];   // unnormalized partial outputs
__device__ float g_pm[NQT * NCH * 128];       // partial row max
__device__ float g_pl[NQT * NCH * 128];       // partial row sum

// ---------------------------------------------------------------------------
__device__ __forceinline__ void mma16816(float* c, const uint32_t* a, const uint32_t* b)
{
    asm volatile(
        "mma.sync.aligned.m16n8k16.row.col.f32.bf16.bf16.f32 "
        "{%0,%1,%2,%3}, {%4,%5,%6,%7}, {%8,%9}, {%0,%1,%2,%3};"
        : "+f"(c[0]), "+f"(c[1]), "+f"(c[2]), "+f"(c[3])
        : "r"(a[0]), "r"(a[1]), "r"(a[2]), "r"(a[3]), "r"(b[0]), "r"(b[1]));
}

__device__ __forceinline__ uint32_t pack_hi(float x, float y, uint32_t& lo)
{
    __nv_bfloat16 hx = __float2bfloat16(x);
    __nv_bfloat16 hy = __float2bfloat16(y);
    __nv_bfloat16 lx = __float2bfloat16(x - __bfloat162float(hx));
    __nv_bfloat16 ly = __float2bfloat16(y - __bfloat162float(hy));
    __nv_bfloat162 l2 = __halves2bfloat162(lx, ly);
    lo = *(uint32_t*)&l2;
    __nv_bfloat162 h2 = __halves2bfloat162(hx, hy);
    return *(uint32_t*)&h2;
}

// ---------------------------------------------------------------------------
// fp32 -> (bf16 hi, bf16 lo) split. dest: 0=X, 1..3=Wq/Wk/Wv
// ---------------------------------------------------------------------------
__global__ __launch_bounds__(256) void cvt_kernel(const float* __restrict__ in,
                                                  int dest, int n)
{
    __nv_bfloat16 *hi, *lo;
    if (dest == 0) { hi = g_Xhi; lo = g_Xlo; }
    else           { hi = g_Whi + (size_t)(dest - 1) * H * DIM;
                     lo = g_Wlo + (size_t)(dest - 1) * H * DIM; }
    int i = (blockIdx.x * 256 + threadIdx.x) * 8;
    if (i >= n) return;
    float4 a = *(const float4*)(in + i);
    float4 b = *(const float4*)(in + i + 4);
    float xs[8] = {a.x, a.y, a.z, a.w, b.x, b.y, b.z, b.w};
    uint4 hv, lv;
    uint32_t* hp = (uint32_t*)&hv;
    uint32_t* lp = (uint32_t*)&lv;
    #pragma unroll
    for (int j = 0; j < 4; j++)
        hp[j] = pack_hi(xs[2 * j], xs[2 * j + 1], lp[j]);
    *(uint4*)(hi + i) = hv;
    *(uint4*)(lo + i) = lv;
}

// ---------------------------------------------------------------------------
// QKV GEMM via mma.sync bf16x3; epilogue emits bf16 hi/lo (Q scaled by 1/sqrt(H))
// BM=128, BN=128(=H), BK=32. 256 threads, warp tile 32m x 64n. grid = (32, 3).
// ---------------------------------------------------------------------------
#define SKS 40
#define QKV_ITERS (DIM / 32)

__global__ __launch_bounds__(256) void qkv_mma_kernel()
{
    __shared__ __nv_bfloat16 sA[2][128 * SKS];
    __shared__ __nv_bfloat16 sB[2][128 * SKS];

    const int tid = threadIdx.x;
    const int wid = tid >> 5;
    const int lid = tid & 31;
    const int wm  = wid & 3;
    const int wn  = wid >> 2;
    const int m0  = blockIdx.x * 128;
    const int widx = blockIdx.y;

    const __nv_bfloat16* Ahi = g_Xhi + (size_t)m0 * DIM;
    const __nv_bfloat16* Alo = g_Xlo + (size_t)m0 * DIM;
    const __nv_bfloat16* Bhi = g_Whi + (size_t)widx * H * DIM;
    const __nv_bfloat16* Blo = g_Wlo + (size_t)widx * H * DIM;

    const int lr = tid >> 2;
    const int lq = tid & 3;

    float acc[2][8][4];
    #pragma unroll
    for (int im = 0; im < 2; im++)
        #pragma unroll
        for (int in = 0; in < 8; in++)
            #pragma unroll
            for (int q = 0; q < 4; q++) acc[im][in][q] = 0.f;

    uint4 rah[2], ral[2], rbh[2], rbl[2];
    #pragma unroll
    for (int g = 0; g < 2; g++) {
        size_t goA = (size_t)(lr + g * 64) * DIM + lq * 8;
        rah[g] = *(const uint4*)(Ahi + goA);
        ral[g] = *(const uint4*)(Alo + goA);
        rbh[g] = *(const uint4*)(Bhi + goA);
        rbl[g] = *(const uint4*)(Blo + goA);
    }

    for (int kc = 0; kc < QKV_ITERS; kc++) {
        __syncthreads();
        #pragma unroll
        for (int g = 0; g < 2; g++) {
            int so = (lr + g * 64) * SKS + lq * 8;
            *(uint4*)&sA[0][so] = rah[g];
            *(uint4*)&sA[1][so] = ral[g];
            *(uint4*)&sB[0][so] = rbh[g];
            *(uint4*)&sB[1][so] = rbl[g];
        }
        __syncthreads();

        if (kc + 1 < QKV_ITERS) {
            #pragma unroll
            for (int g = 0; g < 2; g++) {
                size_t goA = (size_t)(lr + g * 64) * DIM + (kc + 1) * 32 + lq * 8;
                rah[g] = *(const uint4*)(Ahi + goA);
                ral[g] = *(const uint4*)(Alo + goA);
                rbh[g] = *(const uint4*)(Bhi + goA);
                rbl[g] = *(const uint4*)(Blo + goA);
            }
        }

        #pragma unroll
        for (int ks = 0; ks < 2; ks++) {
            const int k0 = ks * 16 + (lid & 3) * 2;
            uint32_t ah[2][4], al[2][4];
            #pragma unroll
            for (int im = 0; im < 2; im++) {
                int r0 = wm * 32 + im * 16 + (lid >> 2);
                ah[im][0] = *(const uint32_t*)&sA[0][r0 * SKS + k0];
                ah[im][1] = *(const uint32_t*)&sA[0][(r0 + 8) * SKS + k0];
                ah[im][2] = *(const uint32_t*)&sA[0][r0 * SKS + k0 + 8];
                ah[im][3] = *(const uint32_t*)&sA[0][(r0 + 8) * SKS + k0 + 8];
                al[im][0] = *(const uint32_t*)&sA[1][r0 * SKS + k0];
                al[im][1] = *(const uint32_t*)&sA[1][(r0 + 8) * SKS + k0];
                al[im][2] = *(const uint32_t*)&sA[1][r0 * SKS + k0 + 8];
                al[im][3] = *(const uint32_t*)&sA[1][(r0 + 8) * SKS + k0 + 8];
            }
            #pragma unroll
            for (int in = 0; in < 8; in++) {
                int n = wn * 64 + in * 8 + (lid >> 2);
                uint32_t bh[2], bl[2];
                bh[0] = *(const uint32_t*)&sB[0][n * SKS + k0];
                bh[1] = *(const uint32_t*)&sB[0][n * SKS + k0 + 8];
                bl[0] = *(const uint32_t*)&sB[1][n * SKS + k0];
                bl[1] = *(const uint32_t*)&sB[1][n * SKS + k0 + 8];
                #pragma unroll
                for (int im = 0; im < 2; im++) {
                    mma16816(acc[im][in], ah[im], bh);
                    mma16816(acc[im][in], ah[im], bl);
                    mma16816(acc[im][in], al[im], bh);
                }
            }
        }
    }

    // epilogue: bf16 hi/lo, Q scaled
    const float scale = (widx == 0) ? 0.08838834764831843f : 1.0f;
    __nv_bfloat16* Ch = (widx == 0) ? g_Qhi : (widx == 1) ? g_Khi : g_Vhi;
    __nv_bfloat16* Cl = (widx == 0) ? g_Qlo : (widx == 1) ? g_Klo : g_Vlo;
    #pragma unroll
    for (int im = 0; im < 2; im++) {
        int r0 = m0 + wm * 32 + im * 16 + (lid >> 2);
        #pragma unroll
        for (int in = 0; in < 8; in++) {
            int c0 = wn * 64 + in * 8 + (lid & 3) * 2;
            uint32_t lo0, lo1;
            uint32_t hi0 = pack_hi(acc[im][in][0] * scale, acc[im][in][1] * scale, lo0);
            uint32_t hi1 = pack_hi(acc[im][in][2] * scale, acc[im][in][3] * scale, lo1);
            *(uint32_t*)&Ch[(size_t)r0 * H + c0] = hi0;
            *(uint32_t*)&Cl[(size_t)r0 * H + c0] = lo0;
            *(uint32_t*)&Ch[(size_t)(r0 + 8) * H + c0] = hi1;
            *(uint32_t*)&Cl[(size_t)(r0 + 8) * H + c0] = lo1;
        }
    }
}

// ---------------------------------------------------------------------------
// Tensor-core split-KV causal flash attention (bf16x3).
// BM=128 queries/block, BN=128 keys/tile, chunk = 4 tiles.
// 8 warps; warp w owns rows w*16..w*16+15 (full 128-col width).
// ---------------------------------------------------------------------------
__global__ __launch_bounds__(256) void attn_partial_kernel()
{
    const int qt = blockIdx.x;          // 0..31
    const int ci = blockIdx.y;          // 0..7
    const int n_kt = qt + 1;
    const int kt0 = ci * 4;
    if (kt0 >= n_kt) return;
    const int kt1 = (kt0 + 4 < n_kt) ? kt0 + 4 : n_kt;

    extern __shared__ __nv_bfloat16 sb[];
    __nv_bfloat16* sQh = sb;
    __nv_bfloat16* sQl = sQh + 128 * SKS2;
    __nv_bfloat16* sKh = sQl + 128 * SKS2;
    __nv_bfloat16* sKl = sKh + 128 * SKS2;
    __nv_bfloat16* sVh = sKl + 128 * SKS2;   // transposed: [feat][key]
    __nv_bfloat16* sVl = sVh + 128 * SKS2;

    const int tid = threadIdx.x;
    const int wid = tid >> 5;
    const int lid = tid & 31;
    const int qr  = lid >> 2;           // quad row 0..7
    const int qc  = lid & 3;            // quad col 0..3

    // ---- load Q (hi/lo), natural layout, stride SKS2 ----
    #pragma unroll
    for (int it = 0; it < 8; it++) {
        int i = tid + it * 256;
        int r = i >> 4, c8 = i & 15;
        *(uint4*)&sQh[r * SKS2 + c8 * 8] =
            *(const uint4*)&g_Qhi[((size_t)qt * 128 + r) * H + c8 * 8];
        *(uint4*)&sQl[r * SKS2 + c8 * 8] =
            *(const uint4*)&g_Qlo[((size_t)qt * 128 + r) * H + c8 * 8];
    }

    float o[16][4];
    #pragma unroll
    for (int nt = 0; nt < 16; nt++)
        #pragma unroll
        for (int q = 0; q < 4; q++) o[nt][q] = 0.f;
    float mi0 = -INFINITY, mi1 = -INFINITY, li0 = 0.f, li1 = 0.f;

    for (int kt = kt0; kt < kt1; kt++) {
        __syncthreads();
        // K natural (hi/lo)
        #pragma unroll
        for (int it = 0; it < 8; it++) {
            int i = tid + it * 256;
            int r = i >> 4, c8 = i & 15;
            *(uint4*)&sKh[r * SKS2 + c8 * 8] =
                *(const uint4*)&g_Khi[((size_t)kt * 128 + r) * H + c8 * 8];
            *(uint4*)&sKl[r * SKS2 + c8 * 8] =
                *(const uint4*)&g_Klo[((size_t)kt * 128 + r) * H + c8 * 8];
        }
        // V transposed: sV[feat][key]
        #pragma unroll
        for (int it = 0; it < 8; it++) {
            int i = tid + it * 256;
            int key = i & 127, fc = i >> 7;
            uint4 hv = *(const uint4*)&g_Vhi[((size_t)kt * 128 + key) * H + fc * 8];
            uint4 lv = *(const uint4*)&g_Vlo[((size_t)kt * 128 + key) * H + fc * 8];
            const __nv_bfloat16* hp = (const __nv_bfloat16*)&hv;
            const __nv_bfloat16* lp = (const __nv_bfloat16*)&lv;
            #pragma unroll
            for (int j = 0; j < 8; j++) {
                sVh[(fc * 8 + j) * SKS2 + key] = hp[j];
                sVl[(fc * 8 + j) * SKS2 + key] = lp[j];
            }
        }
        __syncthreads();

        // ---- S = Q K^T (bf16x3, scale pre-folded into Q) ----
        float s[16][4];
        #pragma unroll
        for (int nt = 0; nt < 16; nt++)
            #pragma unroll
            for (int q = 0; q < 4; q++) s[nt][q] = 0.f;

        #pragma unroll
        for (int ks = 0; ks < 8; ks++) {
            const int k0 = ks * 16 + qc * 2;
            const int r0 = wid * 16 + qr;
            uint32_t ah[4], al[4];
            ah[0] = *(const uint32_t*)&sQh[r0 * SKS2 + k0];
            ah[1] = *(const uint32_t*)&sQh[(r0 + 8) * SKS2 + k0];
            ah[2] = *(const uint32_t*)&sQh[r0 * SKS2 + k0 + 8];
            ah[3] = *(const uint32_t*)&sQh[(r0 + 8) * SKS2 + k0 + 8];
            al[0] = *(const uint32_t*)&sQl[r0 * SKS2 + k0];
            al[1] = *(const uint32_t*)&sQl[(r0 + 8) * SKS2 + k0];
            al[2] = *(const uint32_t*)&sQl[r0 * SKS2 + k0 + 8];
            al[3] = *(const uint32_t*)&sQl[(r0 + 8) * SKS2 + k0 + 8];
            #pragma unroll
            for (int nt = 0; nt < 16; nt++) {
                int n = nt * 8 + qr;
                uint32_t bh[2], bl[2];
                bh[0] = *(const uint32_t*)&sKh[n * SKS2 + k0];
                bh[1] = *(const uint32_t*)&sKh[n * SKS2 + k0 + 8];
                bl[0] = *(const uint32_t*)&sKl[n * SKS2 + k0];
                bl[1] = *(const uint32_t*)&sKl[n * SKS2 + k0 + 8];
                mma16816(s[nt], ah, bh);
                mma16816(s[nt], ah, bl);
                mma16816(s[nt], al, bh);
            }
        }

        // ---- causal mask (only diagonal tile kt == qt) ----
        if (kt == qt) {
            const int rowg0 = qt * 128 + wid * 16 + qr;
            #pragma unroll
            for (int nt = 0; nt < 16; nt++) {
                int colg = kt * 128 + nt * 8 + qc * 2;
                if (colg > rowg0)     s[nt][0] = -INFINITY;
                if (colg + 1 > rowg0) s[nt][1] = -INFINITY;
                if (colg > rowg0 + 8)     s[nt][2] = -INFINITY;
                if (colg + 1 > rowg0 + 8) s[nt][3] = -INFINITY;
            }
        }

        // ---- online softmax (rows fully warp-local; quad shuffles) ----
        float mx0 = -INFINITY, mx1 = -INFINITY;
        #pragma unroll
        for (int nt = 0; nt < 16; nt++) {
            mx0 = fmaxf(mx0, fmaxf(s[nt][0], s[nt][1]));
            mx1 = fmaxf(mx1, fmaxf(s[nt][2], s[nt][3]));
        }
        #pragma unroll
        for (int off = 1; off <= 2; off <<= 1) {
            mx0 = fmaxf(mx0, __shfl_xor_sync(0xffffffffu, mx0, off));
            mx1 = fmaxf(mx1, __shfl_xor_sync(0xffffffffu, mx1, off));
        }
        float mn0 = fmaxf(mi0, mx0), mn1 = fmaxf(mi1, mx1);
        float cor0 = __expf(mi0 - mn0), cor1 = __expf(mi1 - mn1);
        float l0 = 0.f, l1 = 0.f;
        #pragma unroll
        for (int nt = 0; nt < 16; nt++) {
            s[nt][0] = __expf(s[nt][0] - mn0);
            s[nt][1] = __expf(s[nt][1] - mn0);
            s[nt][2] = __expf(s[nt][2] - mn1);
            s[nt][3] = __expf(s[nt][3] - mn1);
            l0 += s[nt][0] + s[nt][1];
            l1 += s[nt][2] + s[nt][3];
        }
        #pragma unroll
        for (int off = 1; off <= 2; off <<= 1) {
            l0 += __shfl_xor_sync(0xffffffffu, l0, off);
            l1 += __shfl_xor_sync(0xffffffffu, l1, off);
        }
        li0 = li0 * cor0 + l0;
        li1 = li1 * cor1 + l1;
        mi0 = mn0; mi1 = mn1;
        #pragma unroll
        for (int nt = 0; nt < 16; nt++) {
            o[nt][0] *= cor0; o[nt][1] *= cor0;
            o[nt][2] *= cor1; o[nt][3] *= cor1;
        }

        // ---- O += P V (P hi/lo from registers, V hi/lo from smem) ----
        #pragma unroll
        for (int ks = 0; ks < 8; ks++) {
            uint32_t ah[4], al[4];
            ah[0] = pack_hi(s[2 * ks][0],     s[2 * ks][1],     al[0]);
            ah[1] = pack_hi(s[2 * ks][2],     s[2 * ks][3],     al[1]);
            ah[2] = pack_hi(s[2 * ks + 1][0], s[2 * ks + 1][1], al[2]);
            ah[3] = pack_hi(s[2 * ks + 1][2], s[2 * ks + 1][3], al[3]);
            const int k0 = ks * 16 + qc * 2;
            #pragma unroll
            for (int nt = 0; nt < 16; nt++) {
                int n = nt * 8 + qr;
                uint32_t bh[2], bl[2];
                bh[0] = *(const uint32_t*)&sVh[n * SKS2 + k0];
                bh[1] = *(const uint32_t*)&sVh[n * SKS2 + k0 + 8];
                bl[0] = *(const uint32_t*)&sVl[n * SKS2 + k0];
                bl[1] = *(const uint32_t*)&sVl[n * SKS2 + k0 + 8];
                mma16816(o[nt], ah, bh);
                mma16816(o[nt], al, bh);
                mma16816(o[nt], ah, bl);
            }
        }
    }

    // ---- write partials ----
    const int slot = qt * NCH + ci;
    const int lr0 = wid * 16 + qr;
    #pragma unroll
    for (int nt = 0; nt < 16; nt++) {
        int c0 = nt * 8 + qc * 2;
        *(float2*)&g_pO[(size_t)slot * 128 * H + lr0 * H + c0] =
            make_float2(o[nt][0], o[nt][1]);
        *(float2*)&g_pO[(size_t)slot * 128 * H + (lr0 + 8) * H + c0] =
            make_float2(o[nt][2], o[nt][3]);
    }
    if (qc == 0) {
        g_pm[slot * 128 + lr0] = mi0;
        g_pm[slot * 128 + lr0 + 8] = mi1;
        g_pl[slot * 128 + lr0] = li0;
        g_pl[slot * 128 + lr0 + 8] = li1;
    }
}

// ---------------------------------------------------------------------------
// Combine partials.  grid = 32 (query tiles of 128 rows), 256 threads.
// ---------------------------------------------------------------------------
__global__ __launch_bounds__(256) void combine_kernel(float* __restrict__ out)
{
    const int qt = blockIdx.x;
    const int n_ch = (qt + 1 + 3) >> 2;

    const int tid = threadIdx.x;
    const int row = tid >> 1;            // 0..127
    const int col0 = (tid & 1) * 64;

    float m[NCH], l[NCH];
    float M = -INFINITY;
    for (int i = 0; i < n_ch; i++) {
        m[i] = g_pm[(qt * NCH + i) * 128 + row];
        l[i] = g_pl[(qt * NCH + i) * 128 + row];
        M = fmaxf(M, m[i]);
    }
    float L = 0.f, w[NCH];
    for (int i = 0; i < n_ch; i++) {
        w[i] = __expf(m[i] - M);
        L += w[i] * l[i];
    }
    const float invL = 1.f / L;

    #pragma unroll
    for (int c4 = 0; c4 < 16; c4++) {
        float4 acc = make_float4(0.f, 0.f, 0.f, 0.f);
        for (int i = 0; i < n_ch; i++) {
            float4 v = *(const float4*)&g_pO[(size_t)(qt * NCH + i) * 128 * H +
                                             row * H + col0 + c4 * 4];
            acc.x += w[i] * v.x; acc.y += w[i] * v.y;
            acc.z += w[i] * v.z; acc.w += w[i] * v.w;
        }
        *(float4*)&out[((size_t)qt * 128 + row) * H + col0 + c4 * 4] =
            make_float4(acc.x * invL, acc.y * invL, acc.z * invL, acc.w * invL);
    }
}

// ---------------------------------------------------------------------------
extern "C" void kernel_launch(void* const* d_in, const int* in_sizes, int n_in,
                              void* d_out, int out_size)
{
    const float* x  = (const float*)d_in[0];
    const float* Wq = (const float*)d_in[1];
    const float* Wk = (const float*)d_in[2];
    const float* Wv = (const float*)d_in[3];
    float* out = (float*)d_out;

    cvt_kernel<<<T_TOK * DIM / 2048, 256>>>(x, 0, T_TOK * DIM);
    cvt_kernel<<<H * DIM / 2048, 256>>>(Wq, 1, H * DIM);
    cvt_kernel<<<H * DIM / 2048, 256>>>(Wk, 2, H * DIM);
    cvt_kernel<<<H * DIM / 2048, 256>>>(Wv, 3, H * DIM);

    qkv_mma_kernel<<<dim3(32, 3), 256>>>();

    const int attn_smem = 6 * 128 * SKS2 * (int)sizeof(__nv_bfloat16);  // 208896
    cudaFuncSetAttribute(attn_partial_kernel,
                         cudaFuncAttributeMaxDynamicSharedMemorySize, attn_smem);
    attn_partial_kernel<<<dim3(NQT, NCH), 256, attn_smem>>>();

    combine_kernel<<<NQT, 256>>>(out);
}

// round 5
// speedup vs baseline: 4.6637x; 1.1838x over previous
#include <cuda_runtime.h>
#include <cuda_bf16.h>
#include <cuda_fp16.h>
#include <math.h>
#include <stdint.h>

#define T_TOK 4096
#define DIM   2048
#define H     128
#define NCH   8        // max KV chunks per query tile (32 key tiles / 4)
#define NQT   32       // query tiles of 128 rows
#define SKS   40       // qkv smem stride (bf16)
#define SKS2  136      // attn smem stride (bf16/half)

// ---------------- device scratch (no allocation allowed) --------------------
__device__ __nv_bfloat16 g_Xhi[T_TOK * DIM];
__device__ __nv_bfloat16 g_Xlo[T_TOK * DIM];
__device__ __nv_bfloat16 g_Whi[3 * H * DIM];
__device__ __nv_bfloat16 g_Wlo[3 * H * DIM];
__device__ __nv_bfloat16 g_Qhi[T_TOK * H], g_Qlo[T_TOK * H];
__device__ __nv_bfloat16 g_Khi[T_TOK * H], g_Klo[T_TOK * H];
__device__ __half        g_Vh[T_TOK * H];
__device__ float g_pO[NQT * NCH * 128 * H];
__device__ float g_pm[NQT * NCH * 128];
__device__ float g_pl[NQT * NCH * 128];

// ---------------- helpers ----------------------------------------------------
__device__ __forceinline__ uint32_t smem_u32(const void* p) {
    uint32_t a;
    asm("{ .reg .u64 t; cvta.to.shared.u64 t, %1; cvt.u32.u64 %0, t; }"
        : "=r"(a) : "l"(p));
    return a;
}
__device__ __forceinline__ void cp16(uint32_t d, const void* s) {
    asm volatile("cp.async.cg.shared.global [%0], [%1], 16;" :: "r"(d), "l"(s));
}
#define CP_COMMIT() asm volatile("cp.async.commit_group;" ::: "memory")
#define CP_WAIT(n)  asm volatile("cp.async.wait_group %0;" :: "n"(n) : "memory")

__device__ __forceinline__ void mma16816(float* c, const uint32_t* a, const uint32_t* b)
{
    asm volatile(
        "mma.sync.aligned.m16n8k16.row.col.f32.bf16.bf16.f32 "
        "{%0,%1,%2,%3}, {%4,%5,%6,%7}, {%8,%9}, {%0,%1,%2,%3};"
        : "+f"(c[0]), "+f"(c[1]), "+f"(c[2]), "+f"(c[3])
        : "r"(a[0]), "r"(a[1]), "r"(a[2]), "r"(a[3]), "r"(b[0]), "r"(b[1]));
}
__device__ __forceinline__ void mma16816h(float* c, const uint32_t* a, const uint32_t* b)
{
    asm volatile(
        "mma.sync.aligned.m16n8k16.row.col.f32.f16.f16.f32 "
        "{%0,%1,%2,%3}, {%4,%5,%6,%7}, {%8,%9}, {%0,%1,%2,%3};"
        : "+f"(c[0]), "+f"(c[1]), "+f"(c[2]), "+f"(c[3])
        : "r"(a[0]), "r"(a[1]), "r"(a[2]), "r"(a[3]), "r"(b[0]), "r"(b[1]));
}
__device__ __forceinline__ void ldsm2t(uint32_t& r0, uint32_t& r1, uint32_t a)
{
    asm volatile("ldmatrix.sync.aligned.m8n8.x2.trans.shared.b16 {%0,%1}, [%2];"
                 : "=r"(r0), "=r"(r1) : "r"(a));
}

__device__ __forceinline__ uint32_t pack_hi(float x, float y, uint32_t& lo)
{
    __nv_bfloat16 hx = __float2bfloat16(x);
    __nv_bfloat16 hy = __float2bfloat16(y);
    __nv_bfloat16 lx = __float2bfloat16(x - __bfloat162float(hx));
    __nv_bfloat16 ly = __float2bfloat16(y - __bfloat162float(hy));
    __nv_bfloat162 l2 = __halves2bfloat162(lx, ly);
    lo = *(uint32_t*)&l2;
    __nv_bfloat162 h2 = __halves2bfloat162(hx, hy);
    return *(uint32_t*)&h2;
}
__device__ __forceinline__ uint32_t pack_h2(float x, float y)
{
    __half2 t = __floats2half2_rn(x, y);
    return *(uint32_t*)&t;
}

// ---------------------------------------------------------------------------
// fp32 -> (bf16 hi, bf16 lo) split. dest: 0=X, 1..3=Wq/Wk/Wv
// ---------------------------------------------------------------------------
__global__ __launch_bounds__(256) void cvt_kernel(const float* __restrict__ in,
                                                  int dest, int n)
{
    __nv_bfloat16 *hi, *lo;
    if (dest == 0) { hi = g_Xhi; lo = g_Xlo; }
    else           { hi = g_Whi + (size_t)(dest - 1) * H * DIM;
                     lo = g_Wlo + (size_t)(dest - 1) * H * DIM; }
    int i = (blockIdx.x * 256 + threadIdx.x) * 8;
    if (i >= n) return;
    float4 a = *(const float4*)(in + i);
    float4 b = *(const float4*)(in + i + 4);
    float xs[8] = {a.x, a.y, a.z, a.w, b.x, b.y, b.z, b.w};
    uint4 hv, lv;
    uint32_t* hp = (uint32_t*)&hv;
    uint32_t* lp = (uint32_t*)&lv;
    #pragma unroll
    for (int j = 0; j < 4; j++)
        hp[j] = pack_hi(xs[2 * j], xs[2 * j + 1], lp[j]);
    *(uint4*)(hi + i) = hv;
    *(uint4*)(lo + i) = lv;
}

// ---------------------------------------------------------------------------
// QKV GEMM, bf16x3, cp.async 2-stage double buffer.
// BM=128, BN=128, BK=32. 256 threads, warp tile 32m x 64n. grid (32,3).
// Epilogue: Q,K -> bf16 hi/lo (Q scaled); V -> fp16 single.
// ---------------------------------------------------------------------------
#define QKV_ITERS (DIM / 32)
#define QKV_STAGE_ELEMS (4 * 128 * SKS)

__global__ __launch_bounds__(256) void qkv_mma_kernel()
{
    extern __shared__ __nv_bfloat16 qsm[];   // 2 stages x (Ah,Al,Bh,Bl) 128xSKS

    const int tid = threadIdx.x;
    const int wid = tid >> 5;
    const int lid = tid & 31;
    const int wm  = wid & 3;
    const int wn  = wid >> 2;
    const int m0  = blockIdx.x * 128;
    const int widx = blockIdx.y;

    const __nv_bfloat16* Ahi = g_Xhi + (size_t)m0 * DIM;
    const __nv_bfloat16* Alo = g_Xlo + (size_t)m0 * DIM;
    const __nv_bfloat16* Bhi = g_Whi + (size_t)widx * H * DIM;
    const __nv_bfloat16* Blo = g_Wlo + (size_t)widx * H * DIM;

    const uint32_t sbase = smem_u32(qsm);
    const uint32_t MAT = 128 * SKS * 2;      // matrix size in bytes

    // async load of one k-slab (BK=32) into stage kc&1
    auto issue = [&](int kc) {
        uint32_t sb = sbase + (uint32_t)(kc & 1) * (4 * MAT);
        #pragma unroll
        for (int g = 0; g < 2; g++) {
            int idx = tid + g * 256;
            int row = idx >> 2, c8 = (idx & 3) * 8;
            size_t go = (size_t)row * DIM + kc * 32 + c8;
            uint32_t dof = (uint32_t)(row * SKS + c8) * 2;
            cp16(sb + dof,           Ahi + go);
            cp16(sb + MAT + dof,     Alo + go);
            cp16(sb + 2 * MAT + dof, Bhi + go);
            cp16(sb + 3 * MAT + dof, Blo + go);
        }
    };

    float acc[2][8][4];
    #pragma unroll
    for (int im = 0; im < 2; im++)
        #pragma unroll
        for (int in = 0; in < 8; in++)
            #pragma unroll
            for (int q = 0; q < 4; q++) acc[im][in][q] = 0.f;

    issue(0); CP_COMMIT();
    issue(1); CP_COMMIT();

    for (int kc = 0; kc < QKV_ITERS; kc++) {
        CP_WAIT(1);
        __syncthreads();

        const __nv_bfloat16* sAh = qsm + (size_t)(kc & 1) * QKV_STAGE_ELEMS;
        const __nv_bfloat16* sAl = sAh + 128 * SKS;
        const __nv_bfloat16* sBh = sAl + 128 * SKS;
        const __nv_bfloat16* sBl = sBh + 128 * SKS;

        #pragma unroll
        for (int ks = 0; ks < 2; ks++) {
            const int k0 = ks * 16 + (lid & 3) * 2;
            uint32_t ah[2][4], al[2][4];
            #pragma unroll
            for (int im = 0; im < 2; im++) {
                int r0 = wm * 32 + im * 16 + (lid >> 2);
                ah[im][0] = *(const uint32_t*)&sAh[r0 * SKS + k0];
                ah[im][1] = *(const uint32_t*)&sAh[(r0 + 8) * SKS + k0];
                ah[im][2] = *(const uint32_t*)&sAh[r0 * SKS + k0 + 8];
                ah[im][3] = *(const uint32_t*)&sAh[(r0 + 8) * SKS + k0 + 8];
                al[im][0] = *(const uint32_t*)&sAl[r0 * SKS + k0];
                al[im][1] = *(const uint32_t*)&sAl[(r0 + 8) * SKS + k0];
                al[im][2] = *(const uint32_t*)&sAl[r0 * SKS + k0 + 8];
                al[im][3] = *(const uint32_t*)&sAl[(r0 + 8) * SKS + k0 + 8];
            }
            #pragma unroll
            for (int in = 0; in < 8; in++) {
                int n = wn * 64 + in * 8 + (lid >> 2);
                uint32_t bh[2], bl[2];
                bh[0] = *(const uint32_t*)&sBh[n * SKS + k0];
                bh[1] = *(const uint32_t*)&sBh[n * SKS + k0 + 8];
                bl[0] = *(const uint32_t*)&sBl[n * SKS + k0];
                bl[1] = *(const uint32_t*)&sBl[n * SKS + k0 + 8];
                #pragma unroll
                for (int im = 0; im < 2; im++) {
                    mma16816(acc[im][in], ah[im], bh);
                    mma16816(acc[im][in], ah[im], bl);
                    mma16816(acc[im][in], al[im], bh);
                }
            }
        }
        __syncthreads();                 // all reads of stage kc&1 done
        if (kc + 2 < QKV_ITERS) issue(kc + 2);
        CP_COMMIT();
    }

    // epilogue
    if (widx == 2) {
        #pragma unroll
        for (int im = 0; im < 2; im++) {
            int r0 = m0 + wm * 32 + im * 16 + (lid >> 2);
            #pragma unroll
            for (int in = 0; in < 8; in++) {
                int c0 = wn * 64 + in * 8 + (lid & 3) * 2;
                *(uint32_t*)&g_Vh[(size_t)r0 * H + c0] =
                    pack_h2(acc[im][in][0], acc[im][in][1]);
                *(uint32_t*)&g_Vh[(size_t)(r0 + 8) * H + c0] =
                    pack_h2(acc[im][in][2], acc[im][in][3]);
            }
        }
    } else {
        const float scale = (widx == 0) ? 0.08838834764831843f : 1.0f;
        __nv_bfloat16* Ch = (widx == 0) ? g_Qhi : g_Khi;
        __nv_bfloat16* Cl = (widx == 0) ? g_Qlo : g_Klo;
        #pragma unroll
        for (int im = 0; im < 2; im++) {
            int r0 = m0 + wm * 32 + im * 16 + (lid >> 2);
            #pragma unroll
            for (int in = 0; in < 8; in++) {
                int c0 = wn * 64 + in * 8 + (lid & 3) * 2;
                uint32_t lo0, lo1;
                uint32_t hi0 = pack_hi(acc[im][in][0] * scale, acc[im][in][1] * scale, lo0);
                uint32_t hi1 = pack_hi(acc[im][in][2] * scale, acc[im][in][3] * scale, lo1);
                *(uint32_t*)&Ch[(size_t)r0 * H + c0] = hi0;
                *(uint32_t*)&Cl[(size_t)r0 * H + c0] = lo0;
                *(uint32_t*)&Ch[(size_t)(r0 + 8) * H + c0] = hi1;
                *(uint32_t*)&Cl[(size_t)(r0 + 8) * H + c0] = lo1;
            }
        }
    }
}

// ---------------------------------------------------------------------------
// Tensor-core split-KV causal flash attention.
// S: bf16x3.  PV: single fp16 (P cvt in regs, V via ldmatrix.trans).
// cp.async pipeline: V(kt) under S-compute, K(kt+1) under softmax+PV.
// ---------------------------------------------------------------------------
__device__ __forceinline__ void attn_issue_tile(uint32_t dst_base,
                                                const void* src_base, int tid)
{
    #pragma unroll
    for (int j = 0; j < 8; j++) {
        int idx = tid + j * 256;
        int row = idx >> 4, c8 = (idx & 15) * 8;
        cp16(dst_base + (uint32_t)(row * SKS2 + c8) * 2,
             (const char*)src_base + ((size_t)row * H + c8) * 2);
    }
}

__global__ __launch_bounds__(256) void attn_partial_kernel()
{
    const int qt = blockIdx.x;
    const int ci = blockIdx.y;
    const int n_kt = qt + 1;
    const int kt0 = ci * 4;
    if (kt0 >= n_kt) return;
    const int kt1 = (kt0 + 4 < n_kt) ? kt0 + 4 : n_kt;

    extern __shared__ char asm_[];
    __nv_bfloat16* sQh = (__nv_bfloat16*)asm_;
    __nv_bfloat16* sQl = sQh + 128 * SKS2;
    __nv_bfloat16* sKh = sQl + 128 * SKS2;
    __nv_bfloat16* sKl = sKh + 128 * SKS2;
    __half*        sV  = (__half*)(sKl + 128 * SKS2);   // natural [key][feat]

    const uint32_t uKh = smem_u32(sKh);
    const uint32_t uKl = smem_u32(sKl);
    const uint32_t uV  = smem_u32(sV);

    const int tid = threadIdx.x;
    const int wid = tid >> 5;
    const int lid = tid & 31;
    const int qr  = lid >> 2;
    const int qc  = lid & 3;

    // prologue: async K(kt0), V(kt0); then Q synchronously
    attn_issue_tile(uKh, g_Khi + (size_t)kt0 * 128 * H, tid);
    attn_issue_tile(uKl, g_Klo + (size_t)kt0 * 128 * H, tid);
    CP_COMMIT();
    attn_issue_tile(uV, g_Vh + (size_t)kt0 * 128 * H, tid);
    CP_COMMIT();

    #pragma unroll
    for (int it = 0; it < 8; it++) {
        int i = tid + it * 256;
        int r = i >> 4, c8 = (i & 15) * 8;
        *(uint4*)&sQh[r * SKS2 + c8] =
            *(const uint4*)&g_Qhi[((size_t)qt * 128 + r) * H + c8];
        *(uint4*)&sQl[r * SKS2 + c8] =
            *(const uint4*)&g_Qlo[((size_t)qt * 128 + r) * H + c8];
    }

    float o[16][4];
    #pragma unroll
    for (int nt = 0; nt < 16; nt++)
        #pragma unroll
        for (int q = 0; q < 4; q++) o[nt][q] = 0.f;
    float mi0 = -INFINITY, mi1 = -INFINITY, li0 = 0.f, li1 = 0.f;

    for (int kt = kt0; kt < kt1; kt++) {
        CP_WAIT(1);              // K(kt) complete (V may still be in flight)
        __syncthreads();

        // ---- S = Q K^T (bf16x3) ----
        float s[16][4];
        #pragma unroll
        for (int nt = 0; nt < 16; nt++)
            #pragma unroll
            for (int q = 0; q < 4; q++) s[nt][q] = 0.f;

        #pragma unroll
        for (int ks = 0; ks < 8; ks++) {
            const int k0 = ks * 16 + qc * 2;
            const int r0 = wid * 16 + qr;
            uint32_t ah[4], al[4];
            ah[0] = *(const uint32_t*)&sQh[r0 * SKS2 + k0];
            ah[1] = *(const uint32_t*)&sQh[(r0 + 8) * SKS2 + k0];
            ah[2] = *(const uint32_t*)&sQh[r0 * SKS2 + k0 + 8];
            ah[3] = *(const uint32_t*)&sQh[(r0 + 8) * SKS2 + k0 + 8];
            al[0] = *(const uint32_t*)&sQl[r0 * SKS2 + k0];
            al[1] = *(const uint32_t*)&sQl[(r0 + 8) * SKS2 + k0];
            al[2] = *(const uint32_t*)&sQl[r0 * SKS2 + k0 + 8];
            al[3] = *(const uint32_t*)&sQl[(r0 + 8) * SKS2 + k0 + 8];
            #pragma unroll
            for (int nt = 0; nt < 16; nt++) {
                int n = nt * 8 + qr;
                uint32_t bh[2], bl[2];
                bh[0] = *(const uint32_t*)&sKh[n * SKS2 + k0];
                bh[1] = *(const uint32_t*)&sKh[n * SKS2 + k0 + 8];
                bl[0] = *(const uint32_t*)&sKl[n * SKS2 + k0];
                bl[1] = *(const uint32_t*)&sKl[n * SKS2 + k0 + 8];
                mma16816(s[nt], ah, bh);
                mma16816(s[nt], ah, bl);
                mma16816(s[nt], al, bh);
            }
        }

        CP_WAIT(0);              // V(kt) complete
        __syncthreads();         // everyone done reading K; V visible
        if (kt + 1 < kt1) {      // K(kt+1) loads overlap softmax + PV
            attn_issue_tile(uKh, g_Khi + (size_t)(kt + 1) * 128 * H, tid);
            attn_issue_tile(uKl, g_Klo + (size_t)(kt + 1) * 128 * H, tid);
        }
        CP_COMMIT();

        // ---- causal mask (diagonal tile only) ----
        if (kt == qt) {
            const int rowg0 = qt * 128 + wid * 16 + qr;
            #pragma unroll
            for (int nt = 0; nt < 16; nt++) {
                int colg = kt * 128 + nt * 8 + qc * 2;
                if (colg > rowg0)         s[nt][0] = -INFINITY;
                if (colg + 1 > rowg0)     s[nt][1] = -INFINITY;
                if (colg > rowg0 + 8)     s[nt][2] = -INFINITY;
                if (colg + 1 > rowg0 + 8) s[nt][3] = -INFINITY;
            }
        }

        // ---- online softmax (quad shuffles) ----
        float mx0 = -INFINITY, mx1 = -INFINITY;
        #pragma unroll
        for (int nt = 0; nt < 16; nt++) {
            mx0 = fmaxf(mx0, fmaxf(s[nt][0], s[nt][1]));
            mx1 = fmaxf(mx1, fmaxf(s[nt][2], s[nt][3]));
        }
        #pragma unroll
        for (int off = 1; off <= 2; off <<= 1) {
            mx0 = fmaxf(mx0, __shfl_xor_sync(0xffffffffu, mx0, off));
            mx1 = fmaxf(mx1, __shfl_xor_sync(0xffffffffu, mx1, off));
        }
        float mn0 = fmaxf(mi0, mx0), mn1 = fmaxf(mi1, mx1);
        float cor0 = __expf(mi0 - mn0), cor1 = __expf(mi1 - mn1);
        float l0 = 0.f, l1 = 0.f;
        #pragma unroll
        for (int nt = 0; nt < 16; nt++) {
            s[nt][0] = __expf(s[nt][0] - mn0);
            s[nt][1] = __expf(s[nt][1] - mn0);
            s[nt][2] = __expf(s[nt][2] - mn1);
            s[nt][3] = __expf(s[nt][3] - mn1);
            l0 += s[nt][0] + s[nt][1];
            l1 += s[nt][2] + s[nt][3];
        }
        #pragma unroll
        for (int off = 1; off <= 2; off <<= 1) {
            l0 += __shfl_xor_sync(0xffffffffu, l0, off);
            l1 += __shfl_xor_sync(0xffffffffu, l1, off);
        }
        li0 = li0 * cor0 + l0;
        li1 = li1 * cor1 + l1;
        mi0 = mn0; mi1 = mn1;
        #pragma unroll
        for (int nt = 0; nt < 16; nt++) {
            o[nt][0] *= cor0; o[nt][1] *= cor0;
            o[nt][2] *= cor1; o[nt][3] *= cor1;
        }

        // ---- O += P V (single fp16; V via ldmatrix.trans) ----
        #pragma unroll
        for (int ks = 0; ks < 8; ks++) {
            uint32_t pa[4];
            pa[0] = pack_h2(s[2 * ks][0],     s[2 * ks][1]);
            pa[1] = pack_h2(s[2 * ks][2],     s[2 * ks][3]);
            pa[2] = pack_h2(s[2 * ks + 1][0], s[2 * ks + 1][1]);
            pa[3] = pack_h2(s[2 * ks + 1][2], s[2 * ks + 1][3]);
            const uint32_t rbase = uV + (uint32_t)((ks * 16 + (lid & 15)) * SKS2) * 2;
            #pragma unroll
            for (int nt = 0; nt < 16; nt++) {
                uint32_t b[2];
                ldsm2t(b[0], b[1], rbase + nt * 16);
                mma16816h(o[nt], pa, b);
            }
        }

        __syncthreads();         // all reads of V done
        if (kt + 1 < kt1)
            attn_issue_tile(uV, g_Vh + (size_t)(kt + 1) * 128 * H, tid);
        CP_COMMIT();
    }

    // ---- write partials ----
    const int slot = qt * NCH + ci;
    const int lr0 = wid * 16 + qr;
    #pragma unroll
    for (int nt = 0; nt < 16; nt++) {
        int c0 = nt * 8 + qc * 2;
        *(float2*)&g_pO[(size_t)slot * 128 * H + lr0 * H + c0] =
            make_float2(o[nt][0], o[nt][1]);
        *(float2*)&g_pO[(size_t)slot * 128 * H + (lr0 + 8) * H + c0] =
            make_float2(o[nt][2], o[nt][3]);
    }
    if (qc == 0) {
        g_pm[slot * 128 + lr0] = mi0;
        g_pm[slot * 128 + lr0 + 8] = mi1;
        g_pl[slot * 128 + lr0] = li0;
        g_pl[slot * 128 + lr0 + 8] = li1;
    }
}

// ---------------------------------------------------------------------------
// Combine partials.  grid = 32, 256 threads.
// ---------------------------------------------------------------------------
__global__ __launch_bounds__(256) void combine_kernel(float* __restrict__ out)
{
    const int qt = blockIdx.x;
    const int n_ch = (qt + 1 + 3) >> 2;

    const int tid = threadIdx.x;
    const int row = tid >> 1;
    const int col0 = (tid & 1) * 64;

    float m[NCH], l[NCH];
    float M = -INFINITY;
    for (int i = 0; i < n_ch; i++) {
        m[i] = g_pm[(qt * NCH + i) * 128 + row];
        l[i] = g_pl[(qt * NCH + i) * 128 + row];
        M = fmaxf(M, m[i]);
    }
    float L = 0.f, w[NCH];
    for (int i = 0; i < n_ch; i++) {
        w[i] = __expf(m[i] - M);
        L += w[i] * l[i];
    }
    const float invL = 1.f / L;

    #pragma unroll
    for (int c4 = 0; c4 < 16; c4++) {
        float4 acc = make_float4(0.f, 0.f, 0.f, 0.f);
        for (int i = 0; i < n_ch; i++) {
            float4 v = *(const float4*)&g_pO[(size_t)(qt * NCH + i) * 128 * H +
                                             row * H + col0 + c4 * 4];
            acc.x += w[i] * v.x; acc.y += w[i] * v.y;
            acc.z += w[i] * v.z; acc.w += w[i] * v.w;
        }
        *(float4*)&out[((size_t)qt * 128 + row) * H + col0 + c4 * 4] =
            make_float4(acc.x * invL, acc.y * invL, acc.z * invL, acc.w * invL);
    }
}

// ---------------------------------------------------------------------------
extern "C" void kernel_launch(void* const* d_in, const int* in_sizes, int n_in,
                              void* d_out, int out_size)
{
    const float* x  = (const float*)d_in[0];
    const float* Wq = (const float*)d_in[1];
    const float* Wk = (const float*)d_in[2];
    const float* Wv = (const float*)d_in[3];
    float* out = (float*)d_out;

    cvt_kernel<<<T_TOK * DIM / 2048, 256>>>(x, 0, T_TOK * DIM);
    cvt_kernel<<<H * DIM / 2048, 256>>>(Wq, 1, H * DIM);
    cvt_kernel<<<H * DIM / 2048, 256>>>(Wk, 2, H * DIM);
    cvt_kernel<<<H * DIM / 2048, 256>>>(Wv, 3, H * DIM);

    const int qkv_smem = 2 * QKV_STAGE_ELEMS * (int)sizeof(__nv_bfloat16); // 81920
    cudaFuncSetAttribute(qkv_mma_kernel,
                         cudaFuncAttributeMaxDynamicSharedMemorySize, qkv_smem);
    qkv_mma_kernel<<<dim3(32, 3), 256, qkv_smem>>>();

    const int attn_smem = 5 * 128 * SKS2 * 2;   // 174080
    cudaFuncSetAttribute(attn_partial_kernel,
                         cudaFuncAttributeMaxDynamicSharedMemorySize, attn_smem);
    attn_partial_kernel<<<dim3(NQT, NCH), 256, attn_smem>>>();

    combine_kernel<<<NQT, 256>>>(out);
}

// round 6
// speedup vs baseline: 5.6580x; 1.2132x over previous
#include <cuda_runtime.h>
#include <cuda_bf16.h>
#include <cuda_fp16.h>
#include <math.h>
#include <stdint.h>

#define T_TOK 4096
#define DIM   2048
#define H     128
#define NCH   8
#define NQT   32
#define SKS   40       // qkv smem stride (bf16)
#define SKS2  136      // attn smem stride (bf16/half)
#define SCALE_F 0.08838834764831843f

// ---------------- device scratch -------------------------------------------
__device__ __nv_bfloat16 g_Xhi[T_TOK * DIM];
__device__ __nv_bfloat16 g_Xlo[T_TOK * DIM];
__device__ __nv_bfloat16 g_Whi[3 * H * DIM];
__device__ __nv_bfloat16 g_Wlo[3 * H * DIM];
__device__ float g_part[9 * T_TOK * H];           // qkv K-split partials
__device__ __nv_bfloat16 g_Qhi[T_TOK * H], g_Qlo[T_TOK * H];
__device__ __nv_bfloat16 g_Khi[T_TOK * H], g_Klo[T_TOK * H];
__device__ __half        g_Vh[T_TOK * H];
__device__ float g_pO[NQT * NCH * 128 * H];
__device__ float g_pm[NQT * NCH * 128];
__device__ float g_pl[NQT * NCH * 128];

// ---------------- helpers ---------------------------------------------------
__device__ __forceinline__ uint32_t smem_u32(const void* p) {
    uint32_t a;
    asm("{ .reg .u64 t; cvta.to.shared.u64 t, %1; cvt.u32.u64 %0, t; }"
        : "=r"(a) : "l"(p));
    return a;
}
__device__ __forceinline__ void cp16(uint32_t d, const void* s) {
    asm volatile("cp.async.cg.shared.global [%0], [%1], 16;" :: "r"(d), "l"(s));
}
#define CP_COMMIT() asm volatile("cp.async.commit_group;" ::: "memory")
#define CP_WAIT(n)  asm volatile("cp.async.wait_group %0;" :: "n"(n) : "memory")

__device__ __forceinline__ void mma16816(float* c, const uint32_t* a, const uint32_t* b)
{
    asm volatile(
        "mma.sync.aligned.m16n8k16.row.col.f32.bf16.bf16.f32 "
        "{%0,%1,%2,%3}, {%4,%5,%6,%7}, {%8,%9}, {%0,%1,%2,%3};"
        : "+f"(c[0]), "+f"(c[1]), "+f"(c[2]), "+f"(c[3])
        : "r"(a[0]), "r"(a[1]), "r"(a[2]), "r"(a[3]), "r"(b[0]), "r"(b[1]));
}
__device__ __forceinline__ void mma16816h(float* c, const uint32_t* a, const uint32_t* b)
{
    asm volatile(
        "mma.sync.aligned.m16n8k16.row.col.f32.f16.f16.f32 "
        "{%0,%1,%2,%3}, {%4,%5,%6,%7}, {%8,%9}, {%0,%1,%2,%3};"
        : "+f"(c[0]), "+f"(c[1]), "+f"(c[2]), "+f"(c[3])
        : "r"(a[0]), "r"(a[1]), "r"(a[2]), "r"(a[3]), "r"(b[0]), "r"(b[1]));
}
__device__ __forceinline__ void ldsm4(uint32_t* r, uint32_t a)
{
    asm volatile("ldmatrix.sync.aligned.m8n8.x4.shared.b16 {%0,%1,%2,%3}, [%4];"
                 : "=r"(r[0]), "=r"(r[1]), "=r"(r[2]), "=r"(r[3]) : "r"(a));
}
__device__ __forceinline__ void ldsm4t(uint32_t* r, uint32_t a)
{
    asm volatile("ldmatrix.sync.aligned.m8n8.x4.trans.shared.b16 {%0,%1,%2,%3}, [%4];"
                 : "=r"(r[0]), "=r"(r[1]), "=r"(r[2]), "=r"(r[3]) : "r"(a));
}
__device__ __forceinline__ uint32_t pack_hi(float x, float y, uint32_t& lo)
{
    __nv_bfloat16 hx = __float2bfloat16(x);
    __nv_bfloat16 hy = __float2bfloat16(y);
    __nv_bfloat16 lx = __float2bfloat16(x - __bfloat162float(hx));
    __nv_bfloat16 ly = __float2bfloat16(y - __bfloat162float(hy));
    __nv_bfloat162 l2 = __halves2bfloat162(lx, ly);
    lo = *(uint32_t*)&l2;
    __nv_bfloat162 h2 = __halves2bfloat162(hx, hy);
    return *(uint32_t*)&h2;
}
__device__ __forceinline__ uint32_t pack_h2(float x, float y)
{
    __half2 t = __floats2half2_rn(x, y);
    return *(uint32_t*)&t;
}

// ---------------------------------------------------------------------------
// fp32 -> (bf16 hi, bf16 lo) split. dest: 0=X, 1..3=Wq/Wk/Wv
// ---------------------------------------------------------------------------
__global__ __launch_bounds__(256) void cvt_kernel(const float* __restrict__ in,
                                                  int dest, int n)
{
    __nv_bfloat16 *hi, *lo;
    if (dest == 0) { hi = g_Xhi; lo = g_Xlo; }
    else           { hi = g_Whi + (size_t)(dest - 1) * H * DIM;
                     lo = g_Wlo + (size_t)(dest - 1) * H * DIM; }
    int i = (blockIdx.x * 256 + threadIdx.x) * 8;
    if (i >= n) return;
    float4 a = *(const float4*)(in + i);
    float4 b = *(const float4*)(in + i + 4);
    float xs[8] = {a.x, a.y, a.z, a.w, b.x, b.y, b.z, b.w};
    uint4 hv, lv;
    uint32_t* hp = (uint32_t*)&hv;
    uint32_t* lp = (uint32_t*)&lv;
    #pragma unroll
    for (int j = 0; j < 4; j++)
        hp[j] = pack_hi(xs[2 * j], xs[2 * j + 1], lp[j]);
    *(uint4*)(hi + i) = hv;
    *(uint4*)(lo + i) = lv;
}

// ---------------------------------------------------------------------------
// QKV GEMM, bf16x3, K-split-3, cp.async double buffer, ldmatrix frags.
// grid (32, 3, 3): M-tile 128, widx, k-third (22/21/21 slabs of BK=32).
// Writes fp32 partials to g_part[(widx*3+z)].
// ---------------------------------------------------------------------------
#define QKV_STAGE_ELEMS (4 * 128 * SKS)

__global__ __launch_bounds__(256, 2) void qkv_mma_kernel()
{
    extern __shared__ __nv_bfloat16 qsm[];

    const int tid = threadIdx.x;
    const int wid = tid >> 5;
    const int lid = tid & 31;
    const int wm  = wid & 3;
    const int wn  = wid >> 2;
    const int m0  = blockIdx.x * 128;
    const int widx = blockIdx.y;
    const int z    = blockIdx.z;

    const int kbeg = (z == 0) ? 0 : (z == 1) ? 22 : 43;
    const int nkc  = (z == 0) ? 22 : 21;

    const __nv_bfloat16* Ahi = g_Xhi + (size_t)m0 * DIM;
    const __nv_bfloat16* Alo = g_Xlo + (size_t)m0 * DIM;
    const __nv_bfloat16* Bhi = g_Whi + (size_t)widx * H * DIM;
    const __nv_bfloat16* Blo = g_Wlo + (size_t)widx * H * DIM;

    const uint32_t sbase = smem_u32(qsm);
    const uint32_t MAT = 128 * SKS * 2;

    auto issue = [&](int i) {
        uint32_t sb = sbase + (uint32_t)(i & 1) * (4 * MAT);
        int kglob = (kbeg + i) * 32;
        #pragma unroll
        for (int g = 0; g < 2; g++) {
            int idx = tid + g * 256;
            int row = idx >> 2, c8 = (idx & 3) * 8;
            size_t go = (size_t)row * DIM + kglob + c8;
            uint32_t dof = (uint32_t)(row * SKS + c8) * 2;
            cp16(sb + dof,           Ahi + go);
            cp16(sb + MAT + dof,     Alo + go);
            cp16(sb + 2 * MAT + dof, Bhi + go);
            cp16(sb + 3 * MAT + dof, Blo + go);
        }
    };

    float acc[2][8][4];
    #pragma unroll
    for (int im = 0; im < 2; im++)
        #pragma unroll
        for (int in = 0; in < 8; in++)
            #pragma unroll
            for (int q = 0; q < 4; q++) acc[im][in][q] = 0.f;

    issue(0); CP_COMMIT();
    issue(1); CP_COMMIT();

    for (int i = 0; i < nkc; i++) {
        CP_WAIT(1);
        __syncthreads();

        const uint32_t uSt = sbase + (uint32_t)(i & 1) * (4 * MAT);
        const uint32_t uAh = uSt, uAl = uSt + MAT;
        const uint32_t uBh = uSt + 2 * MAT, uBl = uSt + 3 * MAT;

        #pragma unroll
        for (int ks = 0; ks < 2; ks++) {
            const int k0 = ks * 16;
            const uint32_t lrow = (lid & 15);
            const uint32_t lcol = k0 + ((lid >> 4) << 3);
            uint32_t ah[2][4], al[2][4];
            #pragma unroll
            for (int im = 0; im < 2; im++) {
                uint32_t aoff = ((wm * 32 + im * 16 + lrow) * SKS + lcol) * 2;
                ldsm4(ah[im], uAh + aoff);
                ldsm4(al[im], uAl + aoff);
            }
            #pragma unroll
            for (int np = 0; np < 4; np++) {
                uint32_t boff = ((wn * 64 + np * 16 + lrow) * SKS + lcol) * 2;
                uint32_t bh4[4], bl4[4];
                ldsm4(bh4, uBh + boff);
                ldsm4(bl4, uBl + boff);
                uint32_t b0h[2] = {bh4[0], bh4[2]}, b1h[2] = {bh4[1], bh4[3]};
                uint32_t b0l[2] = {bl4[0], bl4[2]}, b1l[2] = {bl4[1], bl4[3]};
                #pragma unroll
                for (int im = 0; im < 2; im++) {
                    mma16816(acc[im][2 * np],     ah[im], b0h);
                    mma16816(acc[im][2 * np],     ah[im], b0l);
                    mma16816(acc[im][2 * np],     al[im], b0h);
                    mma16816(acc[im][2 * np + 1], ah[im], b1h);
                    mma16816(acc[im][2 * np + 1], ah[im], b1l);
                    mma16816(acc[im][2 * np + 1], al[im], b1h);
                }
            }
        }
        __syncthreads();
        if (i + 2 < nkc) issue(i + 2);
        CP_COMMIT();
    }

    float* P = g_part + (size_t)(widx * 3 + z) * T_TOK * H + (size_t)m0 * H;
    #pragma unroll
    for (int im = 0; im < 2; im++) {
        int r0 = wm * 32 + im * 16 + (lid >> 2);
        #pragma unroll
        for (int in = 0; in < 8; in++) {
            int c0 = wn * 64 + in * 8 + (lid & 3) * 2;
            *(float2*)&P[(size_t)r0 * H + c0] =
                make_float2(acc[im][in][0], acc[im][in][1]);
            *(float2*)&P[(size_t)(r0 + 8) * H + c0] =
                make_float2(acc[im][in][2], acc[im][in][3]);
        }
    }
}

// ---------------------------------------------------------------------------
// Reduce K-split partials -> Q/K bf16 hi/lo (Q scaled), V fp16.
// grid = 1536, 256 threads, 4 elems/thread.
// ---------------------------------------------------------------------------
__global__ __launch_bounds__(256) void qkv_reduce_kernel()
{
    const int per = T_TOK * H / 4;
    int i4 = blockIdx.x * 256 + threadIdx.x;
    int widx = i4 / per;
    int off = (i4 - widx * per) * 4;
    const float* p0 = g_part + (size_t)(widx * 3 + 0) * (T_TOK * H) + off;
    const float* p1 = g_part + (size_t)(widx * 3 + 1) * (T_TOK * H) + off;
    const float* p2 = g_part + (size_t)(widx * 3 + 2) * (T_TOK * H) + off;
    float4 a = *(const float4*)p0;
    float4 b = *(const float4*)p1;
    float4 c = *(const float4*)p2;
    float v0 = a.x + b.x + c.x, v1 = a.y + b.y + c.y;
    float v2 = a.z + b.z + c.z, v3 = a.w + b.w + c.w;
    if (widx == 2) {
        *(uint32_t*)&g_Vh[off]     = pack_h2(v0, v1);
        *(uint32_t*)&g_Vh[off + 2] = pack_h2(v2, v3);
    } else {
        float sc = (widx == 0) ? SCALE_F : 1.f;
        v0 *= sc; v1 *= sc; v2 *= sc; v3 *= sc;
        __nv_bfloat16* Ch = widx ? g_Khi : g_Qhi;
        __nv_bfloat16* Cl = widx ? g_Klo : g_Qlo;
        uint32_t lo0, lo1;
        uint32_t h0 = pack_hi(v0, v1, lo0);
        uint32_t h1 = pack_hi(v2, v3, lo1);
        *(uint32_t*)&Ch[off]     = h0;
        *(uint32_t*)&Cl[off]     = lo0;
        *(uint32_t*)&Ch[off + 2] = h1;
        *(uint32_t*)&Cl[off + 2] = lo1;
    }
}

// ---------------------------------------------------------------------------
// Tensor-core split-KV causal flash attention; all frags via ldmatrix.
// ---------------------------------------------------------------------------
__device__ __forceinline__ void attn_issue_tile(uint32_t dst_base,
                                                const void* src_base, int tid)
{
    #pragma unroll
    for (int j = 0; j < 8; j++) {
        int idx = tid + j * 256;
        int row = idx >> 4, c8 = (idx & 15) * 8;
        cp16(dst_base + (uint32_t)(row * SKS2 + c8) * 2,
             (const char*)src_base + ((size_t)row * H + c8) * 2);
    }
}

__global__ __launch_bounds__(256) void attn_partial_kernel()
{
    const int qt = blockIdx.x;
    const int ci = blockIdx.y;
    const int n_kt = qt + 1;
    const int kt0 = ci * 4;
    if (kt0 >= n_kt) return;
    const int kt1 = (kt0 + 4 < n_kt) ? kt0 + 4 : n_kt;

    extern __shared__ char asm_[];
    __nv_bfloat16* sQh = (__nv_bfloat16*)asm_;
    __nv_bfloat16* sQl = sQh + 128 * SKS2;
    __nv_bfloat16* sKh = sQl + 128 * SKS2;
    __nv_bfloat16* sKl = sKh + 128 * SKS2;
    __half*        sV  = (__half*)(sKl + 128 * SKS2);

    const uint32_t uQh = smem_u32(sQh);
    const uint32_t uQl = smem_u32(sQl);
    const uint32_t uKh = smem_u32(sKh);
    const uint32_t uKl = smem_u32(sKl);
    const uint32_t uV  = smem_u32(sV);

    const int tid = threadIdx.x;
    const int wid = tid >> 5;
    const int lid = tid & 31;
    const int qr  = lid >> 2;
    const int qc  = lid & 3;
    const uint32_t lrow = (lid & 15);
    const uint32_t lcsh = ((lid >> 4) << 3);

    attn_issue_tile(uKh, g_Khi + (size_t)kt0 * 128 * H, tid);
    attn_issue_tile(uKl, g_Klo + (size_t)kt0 * 128 * H, tid);
    CP_COMMIT();
    attn_issue_tile(uV, g_Vh + (size_t)kt0 * 128 * H, tid);
    CP_COMMIT();

    #pragma unroll
    for (int it = 0; it < 8; it++) {
        int i = tid + it * 256;
        int r = i >> 4, c8 = (i & 15) * 8;
        *(uint4*)&sQh[r * SKS2 + c8] =
            *(const uint4*)&g_Qhi[((size_t)qt * 128 + r) * H + c8];
        *(uint4*)&sQl[r * SKS2 + c8] =
            *(const uint4*)&g_Qlo[((size_t)qt * 128 + r) * H + c8];
    }

    float o[16][4];
    #pragma unroll
    for (int nt = 0; nt < 16; nt++)
        #pragma unroll
        for (int q = 0; q < 4; q++) o[nt][q] = 0.f;
    float mi0 = -INFINITY, mi1 = -INFINITY, li0 = 0.f, li1 = 0.f;

    for (int kt = kt0; kt < kt1; kt++) {
        CP_WAIT(1);
        __syncthreads();

        // ---- S = Q K^T (bf16x3, ldmatrix frags) ----
        float s[16][4];
        #pragma unroll
        for (int nt = 0; nt < 16; nt++)
            #pragma unroll
            for (int q = 0; q < 4; q++) s[nt][q] = 0.f;

        #pragma unroll
        for (int ks = 0; ks < 8; ks++) {
            const uint32_t lcol = ks * 16 + lcsh;
            uint32_t ah[4], al[4];
            uint32_t qoff = ((wid * 16 + lrow) * SKS2 + lcol) * 2;
            ldsm4(ah, uQh + qoff);
            ldsm4(al, uQl + qoff);
            #pragma unroll
            for (int np = 0; np < 8; np++) {
                uint32_t koff = ((np * 16 + lrow) * SKS2 + lcol) * 2;
                uint32_t bh4[4], bl4[4];
                ldsm4(bh4, uKh + koff);
                ldsm4(bl4, uKl + koff);
                uint32_t b0h[2] = {bh4[0], bh4[2]}, b1h[2] = {bh4[1], bh4[3]};
                uint32_t b0l[2] = {bl4[0], bl4[2]}, b1l[2] = {bl4[1], bl4[3]};
                mma16816(s[2 * np],     ah, b0h);
                mma16816(s[2 * np],     ah, b0l);
                mma16816(s[2 * np],     al, b0h);
                mma16816(s[2 * np + 1], ah, b1h);
                mma16816(s[2 * np + 1], ah, b1l);
                mma16816(s[2 * np + 1], al, b1h);
            }
        }

        CP_WAIT(0);
        __syncthreads();
        if (kt + 1 < kt1) {
            attn_issue_tile(uKh, g_Khi + (size_t)(kt + 1) * 128 * H, tid);
            attn_issue_tile(uKl, g_Klo + (size_t)(kt + 1) * 128 * H, tid);
        }
        CP_COMMIT();

        // ---- causal mask (diagonal tile only) ----
        if (kt == qt) {
            const int rowg0 = qt * 128 + wid * 16 + qr;
            #pragma unroll
            for (int nt = 0; nt < 16; nt++) {
                int colg = kt * 128 + nt * 8 + qc * 2;
                if (colg > rowg0)         s[nt][0] = -INFINITY;
                if (colg + 1 > rowg0)     s[nt][1] = -INFINITY;
                if (colg > rowg0 + 8)     s[nt][2] = -INFINITY;
                if (colg + 1 > rowg0 + 8) s[nt][3] = -INFINITY;
            }
        }

        // ---- online softmax ----
        float mx0 = -INFINITY, mx1 = -INFINITY;
        #pragma unroll
        for (int nt = 0; nt < 16; nt++) {
            mx0 = fmaxf(mx0, fmaxf(s[nt][0], s[nt][1]));
            mx1 = fmaxf(mx1, fmaxf(s[nt][2], s[nt][3]));
        }
        #pragma unroll
        for (int off = 1; off <= 2; off <<= 1) {
            mx0 = fmaxf(mx0, __shfl_xor_sync(0xffffffffu, mx0, off));
            mx1 = fmaxf(mx1, __shfl_xor_sync(0xffffffffu, mx1, off));
        }
        float mn0 = fmaxf(mi0, mx0), mn1 = fmaxf(mi1, mx1);
        float cor0 = __expf(mi0 - mn0), cor1 = __expf(mi1 - mn1);
        float l0 = 0.f, l1 = 0.f;
        #pragma unroll
        for (int nt = 0; nt < 16; nt++) {
            s[nt][0] = __expf(s[nt][0] - mn0);
            s[nt][1] = __expf(s[nt][1] - mn0);
            s[nt][2] = __expf(s[nt][2] - mn1);
            s[nt][3] = __expf(s[nt][3] - mn1);
            l0 += s[nt][0] + s[nt][1];
            l1 += s[nt][2] + s[nt][3];
        }
        #pragma unroll
        for (int off = 1; off <= 2; off <<= 1) {
            l0 += __shfl_xor_sync(0xffffffffu, l0, off);
            l1 += __shfl_xor_sync(0xffffffffu, l1, off);
        }
        li0 = li0 * cor0 + l0;
        li1 = li1 * cor1 + l1;
        mi0 = mn0; mi1 = mn1;
        #pragma unroll
        for (int nt = 0; nt < 16; nt++) {
            o[nt][0] *= cor0; o[nt][1] *= cor0;
            o[nt][2] *= cor1; o[nt][3] *= cor1;
        }

        // ---- O += P V (fp16; V ldmatrix.x4.trans) ----
        #pragma unroll
        for (int ks = 0; ks < 8; ks++) {
            uint32_t pa[4];
            pa[0] = pack_h2(s[2 * ks][0],     s[2 * ks][1]);
            pa[1] = pack_h2(s[2 * ks][2],     s[2 * ks][3]);
            pa[2] = pack_h2(s[2 * ks + 1][0], s[2 * ks + 1][1]);
            pa[3] = pack_h2(s[2 * ks + 1][2], s[2 * ks + 1][3]);
            const uint32_t vrow = (ks * 16 + lrow) * SKS2;
            #pragma unroll
            for (int nt2 = 0; nt2 < 16; nt2 += 2) {
                uint32_t b4[4];
                ldsm4t(b4, uV + (vrow + nt2 * 8 + lcsh) * 2);
                mma16816h(o[nt2],     pa, b4);
                mma16816h(o[nt2 + 1], pa, b4 + 2);
            }
        }

        __syncthreads();
        if (kt + 1 < kt1)
            attn_issue_tile(uV, g_Vh + (size_t)(kt + 1) * 128 * H, tid);
        CP_COMMIT();
    }

    const int slot = qt * NCH + ci;
    const int lr0 = wid * 16 + qr;
    #pragma unroll
    for (int nt = 0; nt < 16; nt++) {
        int c0 = nt * 8 + qc * 2;
        *(float2*)&g_pO[(size_t)slot * 128 * H + lr0 * H + c0] =
            make_float2(o[nt][0], o[nt][1]);
        *(float2*)&g_pO[(size_t)slot * 128 * H + (lr0 + 8) * H + c0] =
            make_float2(o[nt][2], o[nt][3]);
    }
    if (qc == 0) {
        g_pm[slot * 128 + lr0] = mi0;
        g_pm[slot * 128 + lr0 + 8] = mi1;
        g_pl[slot * 128 + lr0] = li0;
        g_pl[slot * 128 + lr0 + 8] = li1;
    }
}

// ---------------------------------------------------------------------------
__global__ __launch_bounds__(256) void combine_kernel(float* __restrict__ out)
{
    const int qt = blockIdx.x;
    const int n_ch = (qt + 1 + 3) >> 2;

    const int tid = threadIdx.x;
    const int row = tid >> 1;
    const int col0 = (tid & 1) * 64;

    float m[NCH], l[NCH];
    float M = -INFINITY;
    for (int i = 0; i < n_ch; i++) {
        m[i] = g_pm[(qt * NCH + i) * 128 + row];
        l[i] = g_pl[(qt * NCH + i) * 128 + row];
        M = fmaxf(M, m[i]);
    }
    float L = 0.f, w[NCH];
    for (int i = 0; i < n_ch; i++) {
        w[i] = __expf(m[i] - M);
        L += w[i] * l[i];
    }
    const float invL = 1.f / L;

    #pragma unroll
    for (int c4 = 0; c4 < 16; c4++) {
        float4 acc = make_float4(0.f, 0.f, 0.f, 0.f);
        for (int i = 0; i < n_ch; i++) {
            float4 v = *(const float4*)&g_pO[(size_t)(qt * NCH + i) * 128 * H +
                                             row * H + col0 + c4 * 4];
            acc.x += w[i] * v.x; acc.y += w[i] * v.y;
            acc.z += w[i] * v.z; acc.w += w[i] * v.w;
        }
        *(float4*)&out[((size_t)qt * 128 + row) * H + col0 + c4 * 4] =
            make_float4(acc.x * invL, acc.y * invL, acc.z * invL, acc.w * invL);
    }
}

// ---------------------------------------------------------------------------
extern "C" void kernel_launch(void* const* d_in, const int* in_sizes, int n_in,
                              void* d_out, int out_size)
{
    const float* x  = (const float*)d_in[0];
    const float* Wq = (const float*)d_in[1];
    const float* Wk = (const float*)d_in[2];
    const float* Wv = (const float*)d_in[3];
    float* out = (float*)d_out;

    cvt_kernel<<<T_TOK * DIM / 2048, 256>>>(x, 0, T_TOK * DIM);
    cvt_kernel<<<H * DIM / 2048, 256>>>(Wq, 1, H * DIM);
    cvt_kernel<<<H * DIM / 2048, 256>>>(Wk, 2, H * DIM);
    cvt_kernel<<<H * DIM / 2048, 256>>>(Wv, 3, H * DIM);

    const int qkv_smem = 2 * QKV_STAGE_ELEMS * (int)sizeof(__nv_bfloat16); // 81920
    cudaFuncSetAttribute(qkv_mma_kernel,
                         cudaFuncAttributeMaxDynamicSharedMemorySize, qkv_smem);
    qkv_mma_kernel<<<dim3(32, 3, 3), 256, qkv_smem>>>();

    qkv_reduce_kernel<<<3 * T_TOK * H / 1024, 256>>>();

    const int attn_smem = 5 * 128 * SKS2 * 2;   // 174080
    cudaFuncSetAttribute(attn_partial_kernel,
                         cudaFuncAttributeMaxDynamicSharedMemorySize, attn_smem);
    attn_partial_kernel<<<dim3(NQT, NCH), 256, attn_smem>>>();

    combine_kernel<<<NQT, 256>>>(out);
}

// round 7
// speedup vs baseline: 6.3951x; 1.1303x over previous
#include <cuda_runtime.h>
#include <cuda_bf16.h>
#include <cuda_fp16.h>
#include <math.h>
#include <stdint.h>

#define T_TOK 4096
#define DIM   2048
#define H     128
#define NCH   8
#define NQT   32
#define SKS   40       // qkv smem stride (bf16)
#define SKS2  136      // attn smem stride (bf16/half)
#define SCALE_F 0.08838834764831843f

// ---------------- device scratch -------------------------------------------
__device__ __nv_bfloat16 g_Xhi[T_TOK * DIM];
__device__ __nv_bfloat16 g_Xlo[T_TOK * DIM];
__device__ __nv_bfloat16 g_Whi[3 * H * DIM];
__device__ __nv_bfloat16 g_Wlo[3 * H * DIM];
__device__ float g_part[9 * T_TOK * H];
__device__ __nv_bfloat16 g_Qhi[T_TOK * H], g_Qlo[T_TOK * H];
__device__ __nv_bfloat16 g_Khi[T_TOK * H], g_Klo[T_TOK * H];
__device__ __half        g_Vh[T_TOK * H];
__device__ float g_pO[NQT * NCH * 128 * H];
__device__ float g_pm[NQT * NCH * 128];
__device__ float g_pl[NQT * NCH * 128];

// ---------------- helpers ---------------------------------------------------
__device__ __forceinline__ uint32_t smem_u32(const void* p) {
    uint32_t a;
    asm("{ .reg .u64 t; cvta.to.shared.u64 t, %1; cvt.u32.u64 %0, t; }"
        : "=r"(a) : "l"(p));
    return a;
}
__device__ __forceinline__ void cp16(uint32_t d, const void* s) {
    asm volatile("cp.async.cg.shared.global [%0], [%1], 16;" :: "r"(d), "l"(s));
}
#define CP_COMMIT() asm volatile("cp.async.commit_group;" ::: "memory")
#define CP_WAIT(n)  asm volatile("cp.async.wait_group %0;" :: "n"(n) : "memory")

__device__ __forceinline__ void mma16816(float* c, const uint32_t* a, const uint32_t* b)
{
    asm volatile(
        "mma.sync.aligned.m16n8k16.row.col.f32.bf16.bf16.f32 "
        "{%0,%1,%2,%3}, {%4,%5,%6,%7}, {%8,%9}, {%0,%1,%2,%3};"
        : "+f"(c[0]), "+f"(c[1]), "+f"(c[2]), "+f"(c[3])
        : "r"(a[0]), "r"(a[1]), "r"(a[2]), "r"(a[3]), "r"(b[0]), "r"(b[1]));
}
__device__ __forceinline__ void mma16816h(float* c, const uint32_t* a, const uint32_t* b)
{
    asm volatile(
        "mma.sync.aligned.m16n8k16.row.col.f32.f16.f16.f32 "
        "{%0,%1,%2,%3}, {%4,%5,%6,%7}, {%8,%9}, {%0,%1,%2,%3};"
        : "+f"(c[0]), "+f"(c[1]), "+f"(c[2]), "+f"(c[3])
        : "r"(a[0]), "r"(a[1]), "r"(a[2]), "r"(a[3]), "r"(b[0]), "r"(b[1]));
}
__device__ __forceinline__ void ldsm4(uint32_t* r, uint32_t a)
{
    asm volatile("ldmatrix.sync.aligned.m8n8.x4.shared.b16 {%0,%1,%2,%3}, [%4];"
                 : "=r"(r[0]), "=r"(r[1]), "=r"(r[2]), "=r"(r[3]) : "r"(a));
}
__device__ __forceinline__ void ldsm4t(uint32_t* r, uint32_t a)
{
    asm volatile("ldmatrix.sync.aligned.m8n8.x4.trans.shared.b16 {%0,%1,%2,%3}, [%4];"
                 : "=r"(r[0]), "=r"(r[1]), "=r"(r[2]), "=r"(r[3]) : "r"(a));
}
__device__ __forceinline__ uint32_t pack_hi(float x, float y, uint32_t& lo)
{
    __nv_bfloat16 hx = __float2bfloat16(x);
    __nv_bfloat16 hy = __float2bfloat16(y);
    __nv_bfloat16 lx = __float2bfloat16(x - __bfloat162float(hx));
    __nv_bfloat16 ly = __float2bfloat16(y - __bfloat162float(hy));
    __nv_bfloat162 l2 = __halves2bfloat162(lx, ly);
    lo = *(uint32_t*)&l2;
    __nv_bfloat162 h2 = __halves2bfloat162(hx, hy);
    return *(uint32_t*)&h2;
}
__device__ __forceinline__ uint32_t pack_h2(float x, float y)
{
    __half2 t = __floats2half2_rn(x, y);
    return *(uint32_t*)&t;
}

// ---------------------------------------------------------------------------
// fp32 -> (bf16 hi, bf16 lo) split. dest: 0=X, 1..3=Wq/Wk/Wv
// ---------------------------------------------------------------------------
__global__ __launch_bounds__(256) void cvt_kernel(const float* __restrict__ in,
                                                  int dest, int n)
{
    __nv_bfloat16 *hi, *lo;
    if (dest == 0) { hi = g_Xhi; lo = g_Xlo; }
    else           { hi = g_Whi + (size_t)(dest - 1) * H * DIM;
                     lo = g_Wlo + (size_t)(dest - 1) * H * DIM; }
    int i = (blockIdx.x * 256 + threadIdx.x) * 8;
    if (i >= n) return;
    float4 a = *(const float4*)(in + i);
    float4 b = *(const float4*)(in + i + 4);
    float xs[8] = {a.x, a.y, a.z, a.w, b.x, b.y, b.z, b.w};
    uint4 hv, lv;
    uint32_t* hp = (uint32_t*)&hv;
    uint32_t* lp = (uint32_t*)&lv;
    #pragma unroll
    for (int j = 0; j < 4; j++)
        hp[j] = pack_hi(xs[2 * j], xs[2 * j + 1], lp[j]);
    *(uint4*)(hi + i) = hv;
    *(uint4*)(lo + i) = lv;
}

// ---------------------------------------------------------------------------
// QKV GEMM, bf16x3, K-split-3, cp.async double buffer, ldmatrix frags.
// grid (32, 3, 3).
// ---------------------------------------------------------------------------
#define QKV_STAGE_ELEMS (4 * 128 * SKS)

__global__ __launch_bounds__(256, 2) void qkv_mma_kernel()
{
    extern __shared__ __nv_bfloat16 qsm[];

    const int tid = threadIdx.x;
    const int lid = tid & 31;
    const int wid = tid >> 5;
    const int wm  = wid & 3;
    const int wn  = wid >> 2;
    const int m0  = blockIdx.x * 128;
    const int widx = blockIdx.y;
    const int z    = blockIdx.z;

    const int kbeg = (z == 0) ? 0 : (z == 1) ? 22 : 43;
    const int nkc  = (z == 0) ? 22 : 21;

    const __nv_bfloat16* Ahi = g_Xhi + (size_t)m0 * DIM;
    const __nv_bfloat16* Alo = g_Xlo + (size_t)m0 * DIM;
    const __nv_bfloat16* Bhi = g_Whi + (size_t)widx * H * DIM;
    const __nv_bfloat16* Blo = g_Wlo + (size_t)widx * H * DIM;

    const uint32_t sbase = smem_u32(qsm);
    const uint32_t MAT = 128 * SKS * 2;

    auto issue = [&](int i) {
        uint32_t sb = sbase + (uint32_t)(i & 1) * (4 * MAT);
        int kglob = (kbeg + i) * 32;
        #pragma unroll
        for (int g = 0; g < 2; g++) {
            int idx = tid + g * 256;
            int row = idx >> 2, c8 = (idx & 3) * 8;
            size_t go = (size_t)row * DIM + kglob + c8;
            uint32_t dof = (uint32_t)(row * SKS + c8) * 2;
            cp16(sb + dof,           Ahi + go);
            cp16(sb + MAT + dof,     Alo + go);
            cp16(sb + 2 * MAT + dof, Bhi + go);
            cp16(sb + 3 * MAT + dof, Blo + go);
        }
    };

    float acc[2][8][4];
    #pragma unroll
    for (int im = 0; im < 2; im++)
        #pragma unroll
        for (int in = 0; in < 8; in++)
            #pragma unroll
            for (int q = 0; q < 4; q++) acc[im][in][q] = 0.f;

    issue(0); CP_COMMIT();
    issue(1); CP_COMMIT();

    for (int i = 0; i < nkc; i++) {
        CP_WAIT(1);
        __syncthreads();

        const uint32_t uSt = sbase + (uint32_t)(i & 1) * (4 * MAT);
        const uint32_t uAh = uSt, uAl = uSt + MAT;
        const uint32_t uBh = uSt + 2 * MAT, uBl = uSt + 3 * MAT;

        #pragma unroll
        for (int ks = 0; ks < 2; ks++) {
            const int k0 = ks * 16;
            const uint32_t lrow = (lid & 15);
            const uint32_t lcol = k0 + ((lid >> 4) << 3);
            uint32_t ah[2][4], al[2][4];
            #pragma unroll
            for (int im = 0; im < 2; im++) {
                uint32_t aoff = ((wm * 32 + im * 16 + lrow) * SKS + lcol) * 2;
                ldsm4(ah[im], uAh + aoff);
                ldsm4(al[im], uAl + aoff);
            }
            #pragma unroll
            for (int np = 0; np < 4; np++) {
                uint32_t boff = ((wn * 64 + np * 16 + lrow) * SKS + lcol) * 2;
                uint32_t bh4[4], bl4[4];
                ldsm4(bh4, uBh + boff);
                ldsm4(bl4, uBl + boff);
                uint32_t b0h[2] = {bh4[0], bh4[2]}, b1h[2] = {bh4[1], bh4[3]};
                uint32_t b0l[2] = {bl4[0], bl4[2]}, b1l[2] = {bl4[1], bl4[3]};
                #pragma unroll
                for (int im = 0; im < 2; im++) {
                    mma16816(acc[im][2 * np],     ah[im], b0h);
                    mma16816(acc[im][2 * np],     ah[im], b0l);
                    mma16816(acc[im][2 * np],     al[im], b0h);
                    mma16816(acc[im][2 * np + 1], ah[im], b1h);
                    mma16816(acc[im][2 * np + 1], ah[im], b1l);
                    mma16816(acc[im][2 * np + 1], al[im], b1h);
                }
            }
        }
        __syncthreads();
        if (i + 2 < nkc) issue(i + 2);
        CP_COMMIT();
    }

    float* P = g_part + (size_t)(widx * 3 + z) * T_TOK * H + (size_t)m0 * H;
    #pragma unroll
    for (int im = 0; im < 2; im++) {
        int r0 = wm * 32 + im * 16 + (lid >> 2);
        #pragma unroll
        for (int in = 0; in < 8; in++) {
            int c0 = wn * 64 + in * 8 + (lid & 3) * 2;
            *(float2*)&P[(size_t)r0 * H + c0] =
                make_float2(acc[im][in][0], acc[im][in][1]);
            *(float2*)&P[(size_t)(r0 + 8) * H + c0] =
                make_float2(acc[im][in][2], acc[im][in][3]);
        }
    }
}

// ---------------------------------------------------------------------------
// Reduce K-split partials -> Q/K bf16 hi/lo (Q scaled), V fp16.
// ---------------------------------------------------------------------------
__global__ __launch_bounds__(256) void qkv_reduce_kernel()
{
    const int per = T_TOK * H / 4;
    int i4 = blockIdx.x * 256 + threadIdx.x;
    int widx = i4 / per;
    int off = (i4 - widx * per) * 4;
    const float* p0 = g_part + (size_t)(widx * 3 + 0) * (T_TOK * H) + off;
    const float* p1 = g_part + (size_t)(widx * 3 + 1) * (T_TOK * H) + off;
    const float* p2 = g_part + (size_t)(widx * 3 + 2) * (T_TOK * H) + off;
    float4 a = *(const float4*)p0;
    float4 b = *(const float4*)p1;
    float4 c = *(const float4*)p2;
    float v0 = a.x + b.x + c.x, v1 = a.y + b.y + c.y;
    float v2 = a.z + b.z + c.z, v3 = a.w + b.w + c.w;
    if (widx == 2) {
        *(uint32_t*)&g_Vh[off]     = pack_h2(v0, v1);
        *(uint32_t*)&g_Vh[off + 2] = pack_h2(v2, v3);
    } else {
        float sc = (widx == 0) ? SCALE_F : 1.f;
        v0 *= sc; v1 *= sc; v2 *= sc; v3 *= sc;
        __nv_bfloat16* Ch = widx ? g_Khi : g_Qhi;
        __nv_bfloat16* Cl = widx ? g_Klo : g_Qlo;
        uint32_t lo0, lo1;
        uint32_t h0 = pack_hi(v0, v1, lo0);
        uint32_t h1 = pack_hi(v2, v3, lo1);
        *(uint32_t*)&Ch[off]     = h0;
        *(uint32_t*)&Cl[off]     = lo0;
        *(uint32_t*)&Ch[off + 2] = h1;
        *(uint32_t*)&Cl[off + 2] = lo1;
    }
}

// ---------------------------------------------------------------------------
// Split-KV causal flash attention. Q frags in registers; K and V double-
// buffered; loads issued two tiles ahead.
// smem tiles (each 128 x SKS2 x 2B = 34816B):
//   [0],[1] = Kh buf0/1   [2],[3] = Kl buf0/1   [4],[5] = V buf0/1
// ---------------------------------------------------------------------------
#define TIL 34816u

__device__ __forceinline__ void attn_issue_tile(uint32_t dst_base,
                                                const void* src_base, int tid)
{
    #pragma unroll
    for (int j = 0; j < 8; j++) {
        int idx = tid + j * 256;
        int row = idx >> 4, c8 = (idx & 15) * 8;
        cp16(dst_base + (uint32_t)(row * SKS2 + c8) * 2,
             (const char*)src_base + ((size_t)row * H + c8) * 2);
    }
}

__global__ __launch_bounds__(256) void attn_partial_kernel()
{
    const int qt = blockIdx.x;
    const int ci = blockIdx.y;
    const int n_kt = qt + 1;
    const int kt0 = ci * 4;
    if (kt0 >= n_kt) return;
    const int kt1 = (kt0 + 4 < n_kt) ? kt0 + 4 : n_kt;

    extern __shared__ char asm_[];
    const uint32_t base = smem_u32(asm_);

    const int tid = threadIdx.x;
    const int wid = tid >> 5;
    const int lid = tid & 31;
    const int qr  = lid >> 2;
    const int qc  = lid & 3;
    const uint32_t lrow = (lid & 15);
    const uint32_t lcsh = ((lid >> 4) << 3);

    // ---- prologue: Q -> smem(buf0 K slots) -> registers ----
    attn_issue_tile(base,           g_Qhi + (size_t)qt * 128 * H, tid);
    attn_issue_tile(base + 2 * TIL, g_Qlo + (size_t)qt * 128 * H, tid);
    CP_COMMIT();
    CP_WAIT(0);
    __syncthreads();

    uint32_t qfh[8][4], qfl[8][4];
    #pragma unroll
    for (int ks = 0; ks < 8; ks++) {
        uint32_t qoff = ((wid * 16 + lrow) * SKS2 + ks * 16 + lcsh) * 2;
        ldsm4(qfh[ks], base + qoff);
        ldsm4(qfl[ks], base + 2 * TIL + qoff);
    }
    __syncthreads();   // all warps finished reading Q before K0 overwrites

    // ---- issue G(kt0) and G(kt0+1) ----
    attn_issue_tile(base,           g_Khi + (size_t)kt0 * 128 * H, tid);
    attn_issue_tile(base + 2 * TIL, g_Klo + (size_t)kt0 * 128 * H, tid);
    attn_issue_tile(base + 4 * TIL, g_Vh  + (size_t)kt0 * 128 * H, tid);
    CP_COMMIT();
    if (kt0 + 1 < kt1) {
        attn_issue_tile(base + TIL,     g_Khi + (size_t)(kt0 + 1) * 128 * H, tid);
        attn_issue_tile(base + 3 * TIL, g_Klo + (size_t)(kt0 + 1) * 128 * H, tid);
        attn_issue_tile(base + 5 * TIL, g_Vh  + (size_t)(kt0 + 1) * 128 * H, tid);
    }
    CP_COMMIT();

    float o[16][4];
    #pragma unroll
    for (int nt = 0; nt < 16; nt++)
        #pragma unroll
        for (int q = 0; q < 4; q++) o[nt][q] = 0.f;
    float mi0 = -INFINITY, mi1 = -INFINITY, li0 = 0.f, li1 = 0.f;

    for (int kt = kt0; kt < kt1; kt++) {
        const uint32_t b = (uint32_t)(kt - kt0) & 1;
        const uint32_t uKh = base + b * TIL;
        const uint32_t uKl = base + (2 + b) * TIL;
        const uint32_t uV  = base + (4 + b) * TIL;

        CP_WAIT(1);          // G(kt) complete (G(kt+1) may be in flight)
        __syncthreads();

        // ---- S = Q K^T (bf16x3, Q from regs) ----
        float s[16][4];
        #pragma unroll
        for (int nt = 0; nt < 16; nt++)
            #pragma unroll
            for (int q = 0; q < 4; q++) s[nt][q] = 0.f;

        #pragma unroll
        for (int ks = 0; ks < 8; ks++) {
            const uint32_t lcol = ks * 16 + lcsh;
            #pragma unroll
            for (int np = 0; np < 8; np++) {
                uint32_t koff = ((np * 16 + lrow) * SKS2 + lcol) * 2;
                uint32_t bh4[4], bl4[4];
                ldsm4(bh4, uKh + koff);
                ldsm4(bl4, uKl + koff);
                uint32_t b0h[2] = {bh4[0], bh4[2]}, b1h[2] = {bh4[1], bh4[3]};
                uint32_t b0l[2] = {bl4[0], bl4[2]}, b1l[2] = {bl4[1], bl4[3]};
                mma16816(s[2 * np],     qfh[ks], b0h);
                mma16816(s[2 * np],     qfh[ks], b0l);
                mma16816(s[2 * np],     qfl[ks], b0h);
                mma16816(s[2 * np + 1], qfh[ks], b1h);
                mma16816(s[2 * np + 1], qfh[ks], b1l);
                mma16816(s[2 * np + 1], qfl[ks], b1h);
            }
        }

        // ---- causal mask (diagonal tile only) ----
        if (kt == qt) {
            const int rowg0 = qt * 128 + wid * 16 + qr;
            #pragma unroll
            for (int nt = 0; nt < 16; nt++) {
                int colg = kt * 128 + nt * 8 + qc * 2;
                if (colg > rowg0)         s[nt][0] = -INFINITY;
                if (colg + 1 > rowg0)     s[nt][1] = -INFINITY;
                if (colg > rowg0 + 8)     s[nt][2] = -INFINITY;
                if (colg + 1 > rowg0 + 8) s[nt][3] = -INFINITY;
            }
        }

        // ---- online softmax ----
        float mx0 = -INFINITY, mx1 = -INFINITY;
        #pragma unroll
        for (int nt = 0; nt < 16; nt++) {
            mx0 = fmaxf(mx0, fmaxf(s[nt][0], s[nt][1]));
            mx1 = fmaxf(mx1, fmaxf(s[nt][2], s[nt][3]));
        }
        #pragma unroll
        for (int off = 1; off <= 2; off <<= 1) {
            mx0 = fmaxf(mx0, __shfl_xor_sync(0xffffffffu, mx0, off));
            mx1 = fmaxf(mx1, __shfl_xor_sync(0xffffffffu, mx1, off));
        }
        float mn0 = fmaxf(mi0, mx0), mn1 = fmaxf(mi1, mx1);
        float cor0 = __expf(mi0 - mn0), cor1 = __expf(mi1 - mn1);
        float l0 = 0.f, l1 = 0.f;
        #pragma unroll
        for (int nt = 0; nt < 16; nt++) {
            s[nt][0] = __expf(s[nt][0] - mn0);
            s[nt][1] = __expf(s[nt][1] - mn0);
            s[nt][2] = __expf(s[nt][2] - mn1);
            s[nt][3] = __expf(s[nt][3] - mn1);
            l0 += s[nt][0] + s[nt][1];
            l1 += s[nt][2] + s[nt][3];
        }
        #pragma unroll
        for (int off = 1; off <= 2; off <<= 1) {
            l0 += __shfl_xor_sync(0xffffffffu, l0, off);
            l1 += __shfl_xor_sync(0xffffffffu, l1, off);
        }
        li0 = li0 * cor0 + l0;
        li1 = li1 * cor1 + l1;
        mi0 = mn0; mi1 = mn1;
        #pragma unroll
        for (int nt = 0; nt < 16; nt++) {
            o[nt][0] *= cor0; o[nt][1] *= cor0;
            o[nt][2] *= cor1; o[nt][3] *= cor1;
        }

        // ---- O += P V (fp16; V ldmatrix.x4.trans) ----
        #pragma unroll
        for (int ks = 0; ks < 8; ks++) {
            uint32_t pa[4];
            pa[0] = pack_h2(s[2 * ks][0],     s[2 * ks][1]);
            pa[1] = pack_h2(s[2 * ks][2],     s[2 * ks][3]);
            pa[2] = pack_h2(s[2 * ks + 1][0], s[2 * ks + 1][1]);
            pa[3] = pack_h2(s[2 * ks + 1][2], s[2 * ks + 1][3]);
            const uint32_t vrow = (ks * 16 + lrow) * SKS2;
            #pragma unroll
            for (int nt2 = 0; nt2 < 16; nt2 += 2) {
                uint32_t b4[4];
                ldsm4t(b4, uV + (vrow + nt2 * 8 + lcsh) * 2);
                mma16816h(o[nt2],     pa, b4);
                mma16816h(o[nt2 + 1], pa, b4 + 2);
            }
        }

        __syncthreads();     // all reads of buffer b done
        if (kt + 2 < kt1) {
            attn_issue_tile(base + b * TIL,       g_Khi + (size_t)(kt + 2) * 128 * H, tid);
            attn_issue_tile(base + (2 + b) * TIL, g_Klo + (size_t)(kt + 2) * 128 * H, tid);
            attn_issue_tile(base + (4 + b) * TIL, g_Vh  + (size_t)(kt + 2) * 128 * H, tid);
        }
        CP_COMMIT();         // keep group count aligned (may be empty)
    }

    const int slot = qt * NCH + ci;
    const int lr0 = wid * 16 + qr;
    #pragma unroll
    for (int nt = 0; nt < 16; nt++) {
        int c0 = nt * 8 + qc * 2;
        *(float2*)&g_pO[(size_t)slot * 128 * H + lr0 * H + c0] =
            make_float2(o[nt][0], o[nt][1]);
        *(float2*)&g_pO[(size_t)slot * 128 * H + (lr0 + 8) * H + c0] =
            make_float2(o[nt][2], o[nt][3]);
    }
    if (qc == 0) {
        g_pm[slot * 128 + lr0] = mi0;
        g_pm[slot * 128 + lr0 + 8] = mi1;
        g_pl[slot * 128 + lr0] = li0;
        g_pl[slot * 128 + lr0 + 8] = li1;
    }
}

// ---------------------------------------------------------------------------
// Combine partials. grid = (32, 4): block handles 32 cols of one query tile.
// ---------------------------------------------------------------------------
__global__ __launch_bounds__(256) void combine_kernel(float* __restrict__ out)
{
    const int qt = blockIdx.x;
    const int cg = blockIdx.y;
    const int n_ch = (qt + 1 + 3) >> 2;

    const int tid = threadIdx.x;
    const int row = tid >> 1;                      // 0..127
    const int col0 = cg * 32 + (tid & 1) * 16;     // 16 floats per thread

    float m[NCH], l[NCH];
    float M = -INFINITY;
    for (int i = 0; i < n_ch; i++) {
        m[i] = g_pm[(qt * NCH + i) * 128 + row];
        l[i] = g_pl[(qt * NCH + i) * 128 + row];
        M = fmaxf(M, m[i]);
    }
    float L = 0.f, w[NCH];
    for (int i = 0; i < n_ch; i++) {
        w[i] = __expf(m[i] - M);
        L += w[i] * l[i];
    }
    const float invL = 1.f / L;

    #pragma unroll
    for (int c4 = 0; c4 < 4; c4++) {
        float4 acc = make_float4(0.f, 0.f, 0.f, 0.f);
        for (int i = 0; i < n_ch; i++) {
            float4 v = *(const float4*)&g_pO[(size_t)(qt * NCH + i) * 128 * H +
                                             row * H + col0 + c4 * 4];
            acc.x += w[i] * v.x; acc.y += w[i] * v.y;
            acc.z += w[i] * v.z; acc.w += w[i] * v.w;
        }
        *(float4*)&out[((size_t)qt * 128 + row) * H + col0 + c4 * 4] =
            make_float4(acc.x * invL, acc.y * invL, acc.z * invL, acc.w * invL);
    }
}

// ---------------------------------------------------------------------------
extern "C" void kernel_launch(void* const* d_in, const int* in_sizes, int n_in,
                              void* d_out, int out_size)
{
    const float* x  = (const float*)d_in[0];
    const float* Wq = (const float*)d_in[1];
    const float* Wk = (const float*)d_in[2];
    const float* Wv = (const float*)d_in[3];
    float* out = (float*)d_out;

    cvt_kernel<<<T_TOK * DIM / 2048, 256>>>(x, 0, T_TOK * DIM);
    cvt_kernel<<<H * DIM / 2048, 256>>>(Wq, 1, H * DIM);
    cvt_kernel<<<H * DIM / 2048, 256>>>(Wk, 2, H * DIM);
    cvt_kernel<<<H * DIM / 2048, 256>>>(Wv, 3, H * DIM);

    const int qkv_smem = 2 * QKV_STAGE_ELEMS * (int)sizeof(__nv_bfloat16);
    cudaFuncSetAttribute(qkv_mma_kernel,
                         cudaFuncAttributeMaxDynamicSharedMemorySize, qkv_smem);
    qkv_mma_kernel<<<dim3(32, 3, 3), 256, qkv_smem>>>();

    qkv_reduce_kernel<<<3 * T_TOK * H / 1024, 256>>>();

    const int attn_smem = 6 * (int)TIL;   // 208896
    cudaFuncSetAttribute(attn_partial_kernel,
                         cudaFuncAttributeMaxDynamicSharedMemorySize, attn_smem);
    attn_partial_kernel<<<dim3(NQT, NCH), 256, attn_smem>>>();

    combine_kernel<<<dim3(NQT, 4), 256>>>(out);
}